// round 6
// baseline (speedup 1.0000x reference)
#include <cuda_runtime.h>
#include <cstdint>

#define Ssz   2304
#define Csz   256
#define Bbat  8
#define BSC   (Bbat*Ssz*Csz)
#define SSl   ((long)Ssz*Ssz)
#define ZSTR  (Ssz*Csz)          // 589824, per-batch stride of [b][s][c]

// ---- scratch ---------------------------------------------------------------
__device__ float g_xln[2][BSC];
__device__ float g_q[2][BSC];
__device__ float g_k[2][BSC];
__device__ float g_vt[2][BSC];          // V transposed [b][c][t-perm]
__device__ float g_E[(size_t)Bbat*Ssz*Ssz];
__device__ float g_O[BSC];
__device__ float g_Wtt[4][Csz*Csz];     // W^T [n][k-perm], tf32

// ---- helpers ---------------------------------------------------------------
__device__ __forceinline__ float tf32r(float x) {
    unsigned u; asm("cvt.rna.tf32.f32 %0, %1;" : "=r"(u) : "f"(x));
    return __uint_as_float(u);
}
// k-permutation within 8-blocks: logical k -> stored position
__device__ __forceinline__ int kpi(int k) { return k < 4 ? 2 * k : 2 * k - 7; }

__device__ __forceinline__ void mma_tf32(float acc[4], const unsigned a[4], const unsigned b[2]) {
    asm volatile(
        "mma.sync.aligned.m16n8k8.row.col.f32.tf32.tf32.f32 "
        "{%0,%1,%2,%3}, {%4,%5,%6,%7}, {%8,%9}, {%0,%1,%2,%3};\n"
        : "+f"(acc[0]), "+f"(acc[1]), "+f"(acc[2]), "+f"(acc[3])
        : "r"(a[0]), "r"(a[1]), "r"(a[2]), "r"(a[3]), "r"(b[0]), "r"(b[1]));
}

// stage: A 128x40 = 5120 fl | B(n-major) 256x40 = 10240 fl -> 15360 fl
#define STG_FL  15360
#define SMEM_TC (2*STG_FL*4)     // 122880 B

// ---- weight convert: W[k][n] -> Wtt[n][k-perm], tf32 ------------------------
__global__ void wconv_kernel(const float* __restrict__ wq, const float* __restrict__ wk,
                             const float* __restrict__ wv, const float* __restrict__ wo,
                             float* __restrict__ wt) {
    int mat = blockIdx.y;
    const float* w = mat == 0 ? wq : mat == 1 ? wk : mat == 2 ? wv : wo;
    int n = blockIdx.x, k = threadIdx.x;
    int kp = (k & ~7) | kpi(k & 7);
    wt[mat * 65536 + n * 256 + kp] = tf32r(w[k * 256 + n]);
}

// ---- LayerNorm over C + transpose [B,C,S]->[B,S,C-perm], tf32 out -----------
__global__ __launch_bounds__(256, 2) void ln_kernel(
    const float* __restrict__ xl, const float* __restrict__ xr,
    const float* __restrict__ g1, const float* __restrict__ b1,
    const float* __restrict__ g2, const float* __restrict__ b2,
    float* __restrict__ xlnL, float* __restrict__ xlnR)
{
    const int side = blockIdx.z;
    const float* x  = side ? xr : xl;
    const float* g  = side ? g2 : g1;
    const float* bb = side ? b2 : b1;
    float* xo = side ? xlnR : xlnL;

    const int b  = blockIdx.y;
    const int s0 = blockIdx.x * 32;
    const int tid = threadIdx.x;
    const int tx = tid & 31, ty = tid >> 5;

    __shared__ float xs[256][33];
    __shared__ float ps[8][32], ps2[8][32];
    __shared__ float mu[32], rs[32];

    const float* xb = x + (size_t)b * Csz * Ssz;
    #pragma unroll
    for (int cc = 0; cc < 32; cc++) {
        int c = cc * 8 + ty;
        xs[c][tx] = xb[(size_t)c * Ssz + s0 + tx];
    }
    __syncthreads();

    float sum = 0.f, sq = 0.f;
    #pragma unroll
    for (int i = 0; i < 32; i++) {
        float v = xs[ty * 32 + i][tx];
        sum += v; sq += v * v;
    }
    ps[ty][tx] = sum; ps2[ty][tx] = sq;
    __syncthreads();

    if (ty == 0) {
        float s1 = 0.f, s2 = 0.f;
        #pragma unroll
        for (int j = 0; j < 8; j++) { s1 += ps[j][tx]; s2 += ps2[j][tx]; }
        float m = s1 * (1.f / 256.f);
        float v = s2 * (1.f / 256.f) - m * m;
        mu[tx] = m;
        rs[tx] = rsqrtf(v + 1e-5f);
    }
    __syncthreads();

    const float gc = g[tid], bc = bb[tid];
    const int cperm = (tid & ~7) | kpi(tid & 7);
    float* xob = xo + ((size_t)b * Ssz + s0) * Csz;
    #pragma unroll
    for (int si = 0; si < 32; si++)
        xob[si * Csz + cperm] = tf32r((xs[tid][si] - mu[si]) * rs[si] * gc + bc);
}

// ---- TF32 GEMM: C[M,256] = A[M,K] @ Bt[N,K]^T (both k-perm, k contiguous) --
// CTA 128x256, 8 warps (2m x 4n), warp 64x64, K-chunk 32, double-buffered.
// MODE 0: C = tf32(acc) with n-axis k-permuted (Q, K, O)
// MODE 1: Vt[(b*256+c)*S + t-perm] = tf32(acc)     (V projection, transposed)
// MODE 2: out[(b*256+c)*S + s] = resid + acc       (final, no perm)
template<int MODE>
__global__ __launch_bounds__(256) void gemm_tc(
    const float* __restrict__ A, int lda, long sA,
    const float* __restrict__ Bt, int ldb, long sB,
    float* __restrict__ C, long sC, int K,
    const float* __restrict__ resid)
{
    extern __shared__ float sm[];
    const int tid = threadIdx.x, lane = tid & 31, wid = tid >> 5;
    const int grp = lane >> 2, tg = lane & 3;
    const int wm = (wid & 1) * 64, wn = (wid >> 1) * 64;
    const int m0 = blockIdx.x * 128;
    const int z = blockIdx.y;
    A  += (long)z * sA;
    Bt += (long)z * sB;
    C  += (long)z * sC;

    const int lr = tid >> 3, lc = (tid & 7) * 4;
    float4 ra[4], rb[8];

    auto ldg = [&](int kc) {
        #pragma unroll
        for (int p = 0; p < 4; p++)
            ra[p] = *(const float4*)&A[(long)(m0 + lr + p * 32) * lda + kc * 32 + lc];
        #pragma unroll
        for (int p = 0; p < 8; p++)
            rb[p] = *(const float4*)&Bt[(long)(lr + p * 32) * ldb + kc * 32 + lc];
    };
    auto sts = [&](int stg) {
        float* As = sm + stg * STG_FL;
        float* Bs = As + 5120;
        #pragma unroll
        for (int p = 0; p < 4; p++)
            *(float4*)&As[(lr + p * 32) * 40 + lc] = ra[p];
        #pragma unroll
        for (int p = 0; p < 8; p++)
            *(float4*)&Bs[(lr + p * 32) * 40 + lc] = rb[p];
    };

    float acc[4][8][4];
    #pragma unroll
    for (int i = 0; i < 4; i++)
        #pragma unroll
        for (int j = 0; j < 8; j++)
            #pragma unroll
            for (int r = 0; r < 4; r++) acc[i][j][r] = 0.f;

    const int nch = K >> 5;
    ldg(0); sts(0); __syncthreads();

    for (int ic = 0; ic < nch; ic++) {
        const int stg = ic & 1;
        if (ic + 1 < nch) ldg(ic + 1);

        const float* As = sm + stg * STG_FL;
        const float* Bs = As + 5120;
        #pragma unroll
        for (int ks = 0; ks < 4; ks++) {
            const int k0 = ks * 8;
            unsigned af[4][4], bf[8][2];
            #pragma unroll
            for (int mi = 0; mi < 4; mi++) {
                int rm = wm + mi * 16;
                float2 a0 = *(const float2*)&As[(rm + grp    ) * 40 + k0 + 2 * tg];
                float2 a1 = *(const float2*)&As[(rm + grp + 8) * 40 + k0 + 2 * tg];
                af[mi][0] = __float_as_uint(a0.x);
                af[mi][1] = __float_as_uint(a1.x);
                af[mi][2] = __float_as_uint(a0.y);
                af[mi][3] = __float_as_uint(a1.y);
            }
            #pragma unroll
            for (int ni = 0; ni < 8; ni++) {
                int cn = wn + ni * 8 + grp;
                float2 b0 = *(const float2*)&Bs[cn * 40 + k0 + 2 * tg];
                bf[ni][0] = __float_as_uint(b0.x);
                bf[ni][1] = __float_as_uint(b0.y);
            }
            #pragma unroll
            for (int mi = 0; mi < 4; mi++)
                #pragma unroll
                for (int ni = 0; ni < 8; ni++)
                    mma_tf32(acc[mi][ni], af[mi], bf[ni]);
        }
        if (ic + 1 < nch) { sts(stg ^ 1); __syncthreads(); }
    }

    const int p0 = kpi(2 * tg), p1 = kpi(2 * tg + 1);
    #pragma unroll
    for (int mi = 0; mi < 4; mi++) {
        #pragma unroll
        for (int ni = 0; ni < 8; ni++) {
            int r0 = m0 + wm + mi * 16 + grp;
            if (MODE == 0) {
                int cb = wn + ni * 8;
                C[(long)r0 * 256 + cb + p0]       = tf32r(acc[mi][ni][0]);
                C[(long)r0 * 256 + cb + p1]       = tf32r(acc[mi][ni][1]);
                C[(long)(r0 + 8) * 256 + cb + p0] = tf32r(acc[mi][ni][2]);
                C[(long)(r0 + 8) * 256 + cb + p1] = tf32r(acc[mi][ni][3]);
            } else if (MODE == 1) {
                int bb = r0 / Ssz;
                int t  = r0 - bb * Ssz;
                int tp = t - grp + kpi(grp);
                int c0 = wn + ni * 8 + 2 * tg;
                C[((long)(bb * 256 + c0    )) * Ssz + tp    ] = tf32r(acc[mi][ni][0]);
                C[((long)(bb * 256 + c0 + 1)) * Ssz + tp    ] = tf32r(acc[mi][ni][1]);
                C[((long)(bb * 256 + c0    )) * Ssz + tp + 8] = tf32r(acc[mi][ni][2]);
                C[((long)(bb * 256 + c0 + 1)) * Ssz + tp + 8] = tf32r(acc[mi][ni][3]);
            } else {
                int bb = r0 / Ssz;
                int ss = r0 - bb * Ssz;
                int c0 = wn + ni * 8 + 2 * tg;
                long a0 = ((long)(bb * 256 + c0)) * Ssz + ss;
                C[a0          ] = resid[a0          ] + acc[mi][ni][0];
                C[a0 + Ssz    ] = resid[a0 + Ssz    ] + acc[mi][ni][1];
                C[a0 + 8      ] = resid[a0 + 8      ] + acc[mi][ni][2];
                C[a0 + Ssz + 8] = resid[a0 + Ssz + 8] + acc[mi][ni][3];
            }
        }
    }
}

// ---- scores + fused batch softmax ------------------------------------------
// CTA 128s x 256t; loops 8 batches in-CTA; writes raw exp() per batch, then
// (same CTA) sums over batches and rescales its tile in place (tf32, t-perm).
__global__ __launch_bounds__(256) void tc_scores(
    const float* __restrict__ Q, const float* __restrict__ Ko,
    float* __restrict__ E)
{
    extern __shared__ float sm[];
    const int tid = threadIdx.x, lane = tid & 31, wid = tid >> 5;
    const int grp = lane >> 2, tg = lane & 3;
    const int wm = (wid & 1) * 64, wn = (wid >> 1) * 64;
    const int s0 = blockIdx.y * 128, t0 = blockIdx.x * 256;

    const int lr = tid >> 3, lc = (tid & 7) * 4;
    float4 ra[4], rk[8];

    auto ldg = [&](int it) {
        int b = it >> 3, kc = it & 7;
        const float* qa = Q  + ((long)b * Ssz + s0) * 256;
        const float* kb = Ko + ((long)b * Ssz + t0) * 256;
        #pragma unroll
        for (int p = 0; p < 4; p++)
            ra[p] = *(const float4*)&qa[(long)(lr + p * 32) * 256 + kc * 32 + lc];
        #pragma unroll
        for (int p = 0; p < 8; p++)
            rk[p] = *(const float4*)&kb[(long)(lr + p * 32) * 256 + kc * 32 + lc];
    };
    auto sts = [&](int stg) {
        float* Qs = sm + stg * STG_FL;
        float* Ks = Qs + 5120;
        #pragma unroll
        for (int p = 0; p < 4; p++)
            *(float4*)&Qs[(lr + p * 32) * 40 + lc] = ra[p];
        #pragma unroll
        for (int p = 0; p < 8; p++)
            *(float4*)&Ks[(lr + p * 32) * 40 + lc] = rk[p];
    };

    float acc[4][8][4];
    ldg(0); sts(0); __syncthreads();

    const int p0 = kpi(2 * tg), p1 = kpi(2 * tg + 1);

    for (int it = 0; it < 64; it++) {
        const int stg = it & 1;
        if (it + 1 < 64) ldg(it + 1);

        if ((it & 7) == 0) {
            #pragma unroll
            for (int i = 0; i < 4; i++)
                #pragma unroll
                for (int j = 0; j < 8; j++)
                    #pragma unroll
                    for (int r = 0; r < 4; r++) acc[i][j][r] = 0.f;
        }

        const float* Qs = sm + stg * STG_FL;
        const float* Ks = Qs + 5120;
        #pragma unroll
        for (int ks = 0; ks < 4; ks++) {
            const int k0 = ks * 8;
            unsigned af[4][4], bf[8][2];
            #pragma unroll
            for (int mi = 0; mi < 4; mi++) {
                int rm = wm + mi * 16;
                float2 a0 = *(const float2*)&Qs[(rm + grp    ) * 40 + k0 + 2 * tg];
                float2 a1 = *(const float2*)&Qs[(rm + grp + 8) * 40 + k0 + 2 * tg];
                af[mi][0] = __float_as_uint(a0.x);
                af[mi][1] = __float_as_uint(a1.x);
                af[mi][2] = __float_as_uint(a0.y);
                af[mi][3] = __float_as_uint(a1.y);
            }
            #pragma unroll
            for (int ni = 0; ni < 8; ni++) {
                int cn = wn + ni * 8 + grp;
                float2 b0 = *(const float2*)&Ks[cn * 40 + k0 + 2 * tg];
                bf[ni][0] = __float_as_uint(b0.x);
                bf[ni][1] = __float_as_uint(b0.y);
            }
            #pragma unroll
            for (int mi = 0; mi < 4; mi++)
                #pragma unroll
                for (int ni = 0; ni < 8; ni++)
                    mma_tf32(acc[mi][ni], af[mi], bf[ni]);
        }

        if ((it & 7) == 7) {
            const int b = it >> 3;
            float* Eb = E + (long)b * SSl;
            #pragma unroll
            for (int mi = 0; mi < 4; mi++) {
                #pragma unroll
                for (int ni = 0; ni < 8; ni++) {
                    int r0 = s0 + wm + mi * 16 + grp;
                    int cb = t0 + wn + ni * 8;
                    Eb[(long)r0 * Ssz + cb + p0] =
                        __expf(acc[mi][ni][0] * 0.0625f);
                    Eb[(long)r0 * Ssz + cb + p1] =
                        __expf(acc[mi][ni][1] * 0.0625f);
                    Eb[(long)(r0 + 8) * Ssz + cb + p0] =
                        __expf(acc[mi][ni][2] * 0.0625f);
                    Eb[(long)(r0 + 8) * Ssz + cb + p1] =
                        __expf(acc[mi][ni][3] * 0.0625f);
                }
            }
        }
        if (it + 1 < 64) { sts(stg ^ 1); __syncthreads(); }
    }

    // fused batch-softmax normalization of this CTA's 128x256 tile (L2-hot)
    __threadfence_block();
    __syncthreads();

    #pragma unroll 4
    for (int p = 0; p < 32; p++) {
        int u = p * 256 + tid;
        int rr = u >> 6;
        int cc = (u & 63) * 4;
        long a = (long)(s0 + rr) * Ssz + t0 + cc;
        float4 e[Bbat];
        float4 s = make_float4(0.f, 0.f, 0.f, 0.f);
        #pragma unroll
        for (int b = 0; b < Bbat; b++) {
            e[b] = *(const float4*)&E[b * SSl + a];
            s.x += e[b].x; s.y += e[b].y; s.z += e[b].z; s.w += e[b].w;
        }
        float4 inv = make_float4(1.f / s.x, 1.f / s.y, 1.f / s.z, 1.f / s.w);
        #pragma unroll
        for (int b = 0; b < Bbat; b++) {
            *(float4*)&E[b * SSl + a] =
                make_float4(tf32r(e[b].x * inv.x), tf32r(e[b].y * inv.y),
                            tf32r(e[b].z * inv.z), tf32r(e[b].w * inv.w));
        }
    }
}

// ---- launch ----------------------------------------------------------------
extern "C" void kernel_launch(void* const* d_in, const int* in_sizes, int n_in,
                              void* d_out, int out_size) {
    const float* x_l = (const float*)d_in[0];
    const float* x_r = (const float*)d_in[1];
    const float* Wq  = (const float*)d_in[2];
    const float* Wk  = (const float*)d_in[3];
    const float* Wv  = (const float*)d_in[4];
    const float* Wo  = (const float*)d_in[5];
    const float* g1  = (const float*)d_in[6];
    const float* b1  = (const float*)d_in[7];
    const float* g2  = (const float*)d_in[8];
    const float* b2  = (const float*)d_in[9];
    float* out = (float*)d_out;

    float *xln, *q, *k, *vt, *E, *O, *Wtt;
    cudaGetSymbolAddress((void**)&xln, g_xln);
    cudaGetSymbolAddress((void**)&q,   g_q);
    cudaGetSymbolAddress((void**)&k,   g_k);
    cudaGetSymbolAddress((void**)&vt,  g_vt);
    cudaGetSymbolAddress((void**)&E,   g_E);
    cudaGetSymbolAddress((void**)&O,   g_O);
    cudaGetSymbolAddress((void**)&Wtt, g_Wtt);

    cudaFuncSetAttribute(gemm_tc<0>, cudaFuncAttributeMaxDynamicSharedMemorySize, SMEM_TC);
    cudaFuncSetAttribute(gemm_tc<1>, cudaFuncAttributeMaxDynamicSharedMemorySize, SMEM_TC);
    cudaFuncSetAttribute(gemm_tc<2>, cudaFuncAttributeMaxDynamicSharedMemorySize, SMEM_TC);
    cudaFuncSetAttribute(tc_scores,  cudaFuncAttributeMaxDynamicSharedMemorySize, SMEM_TC);

    wconv_kernel<<<dim3(256, 4), 256>>>(Wq, Wk, Wv, Wo, Wtt);
    ln_kernel<<<dim3(Ssz / 32, Bbat, 2), 256>>>(x_l, x_r, g1, b1, g2, b2,
                                                xln, xln + BSC);

    for (int s = 0; s < 2; s++) {
        gemm_tc<0><<<dim3(144, 1), 256, SMEM_TC>>>(xln + s * BSC, 256, 0,
                                                   Wtt + 0 * 65536, 256, 0,
                                                   q + s * BSC, 0, 256, nullptr);
        gemm_tc<0><<<dim3(144, 1), 256, SMEM_TC>>>(xln + s * BSC, 256, 0,
                                                   Wtt + 1 * 65536, 256, 0,
                                                   k + s * BSC, 0, 256, nullptr);
        gemm_tc<1><<<dim3(144, 1), 256, SMEM_TC>>>(xln + s * BSC, 256, 0,
                                                   Wtt + 2 * 65536, 256, 0,
                                                   vt + s * BSC, 0, 256, nullptr);
    }

    for (int s = 0; s < 2; s++) {
        tc_scores<<<dim3(9, 18), 256, SMEM_TC>>>(q + s * BSC, k + (1 - s) * BSC, E);
        gemm_tc<0><<<dim3(18, 8), 256, SMEM_TC>>>(E, Ssz, SSl,
                                                  vt + s * BSC, Ssz, (long)ZSTR,
                                                  O, (long)ZSTR, Ssz, nullptr);
        gemm_tc<2><<<dim3(144, 1), 256, SMEM_TC>>>(O, 256, 0,
                                                   Wtt + 3 * 65536, 256, 0,
                                                   out + s * BSC, 0, 256,
                                                   s ? x_r : x_l);
    }
}

// round 7
// speedup vs baseline: 1.1767x; 1.1767x over previous
#include <cuda_runtime.h>
#include <cstdint>

#define Ssz   2304
#define Csz   256
#define Bbat  8
#define BSC   (Bbat*Ssz*Csz)
#define SSl   ((long)Ssz*Ssz)

// ---- scratch ---------------------------------------------------------------
__device__ float g_xln[2][BSC];
__device__ float g_q[2][BSC];
__device__ float g_k[2][BSC];
__device__ float g_v[2][BSC];
__device__ float g_E[(size_t)Bbat*Ssz*Ssz];
__device__ float g_O[BSC];
__device__ float g_Wt[4][Csz*Csz];

// ---- helpers ---------------------------------------------------------------
__device__ __forceinline__ float tf32r(float x) {
    unsigned u; asm("cvt.rna.tf32.f32 %0, %1;" : "=r"(u) : "f"(x));
    return __uint_as_float(u);
}
__device__ __forceinline__ void mma_tf32(float acc[4], const unsigned a[4], const unsigned b[2]) {
    asm volatile(
        "mma.sync.aligned.m16n8k8.row.col.f32.tf32.tf32.f32 "
        "{%0,%1,%2,%3}, {%4,%5,%6,%7}, {%8,%9}, {%0,%1,%2,%3};\n"
        : "+f"(acc[0]), "+f"(acc[1]), "+f"(acc[2]), "+f"(acc[3])
        : "r"(a[0]), "r"(a[1]), "r"(a[2]), "r"(a[3]), "r"(b[0]), "r"(b[1]));
}

// stage layouts (floats):
//  gemm:   As 128*36 = 4608 | Bs 32*264 = 8448  -> 13056 fl (52224 B)
//  scores: Qs 128*36 = 4608 | Ks 256*36 = 9216  -> 13824 fl (55296 B)
#define G_STG   13056
#define S_STG   13824
#define SMEM_G  (2*G_STG*4)
#define SMEM_S  (2*S_STG*4)

// ---- weight convert: tf32 round, W stays [k][n] ----------------------------
__global__ void wconv_kernel(const float* __restrict__ wq, const float* __restrict__ wk,
                             const float* __restrict__ wv, const float* __restrict__ wo,
                             float* __restrict__ wt) {
    int i = blockIdx.x * 256 + threadIdx.x;
    wt[0*Csz*Csz + i] = tf32r(wq[i]);
    wt[1*Csz*Csz + i] = tf32r(wk[i]);
    wt[2*Csz*Csz + i] = tf32r(wv[i]);
    wt[3*Csz*Csz + i] = tf32r(wo[i]);
}

// ---- LayerNorm over C + transpose [B,C,S]->[B,S,C], tf32 out ---------------
__global__ __launch_bounds__(256, 2) void ln_kernel(
    const float* __restrict__ xl, const float* __restrict__ xr,
    const float* __restrict__ g1, const float* __restrict__ b1,
    const float* __restrict__ g2, const float* __restrict__ b2,
    float* __restrict__ xlnL, float* __restrict__ xlnR)
{
    const int side = blockIdx.z;
    const float* x  = side ? xr : xl;
    const float* g  = side ? g2 : g1;
    const float* bb = side ? b2 : b1;
    float* xo = side ? xlnR : xlnL;

    const int b  = blockIdx.y;
    const int s0 = blockIdx.x * 32;
    const int tid = threadIdx.x;
    const int tx = tid & 31, ty = tid >> 5;

    __shared__ float xs[256][33];
    __shared__ float ps[8][32], ps2[8][32];
    __shared__ float mu[32], rs[32];

    const float* xb = x + (size_t)b * Csz * Ssz;
    #pragma unroll
    for (int cc = 0; cc < 32; cc++) {
        int c = cc * 8 + ty;
        xs[c][tx] = xb[(size_t)c * Ssz + s0 + tx];
    }
    __syncthreads();

    float sum = 0.f, sq = 0.f;
    #pragma unroll
    for (int i = 0; i < 32; i++) {
        float v = xs[ty * 32 + i][tx];
        sum += v; sq += v * v;
    }
    ps[ty][tx] = sum; ps2[ty][tx] = sq;
    __syncthreads();

    if (ty == 0) {
        float s1 = 0.f, s2 = 0.f;
        #pragma unroll
        for (int j = 0; j < 8; j++) { s1 += ps[j][tx]; s2 += ps2[j][tx]; }
        float m = s1 * (1.f / 256.f);
        float v = s2 * (1.f / 256.f) - m * m;
        mu[tx] = m;
        rs[tx] = rsqrtf(v + 1e-5f);
    }
    __syncthreads();

    const float gc = g[tid], bc = bb[tid];
    float* xob = xo + ((size_t)b * Ssz + s0) * Csz;
    #pragma unroll
    for (int si = 0; si < 32; si++)
        xob[si * Csz + tid] = tf32r((xs[tid][si] - mu[si]) * rs[si] * gc + bc);
}

// ---- TF32 GEMM: C[M,256] = A[M,K] @ B[K,256] -------------------------------
// CTA 128x256, 512 threads, 16 warps (2m x 8n), warp tile 64x32, K-chunk 32,
// double-buffered smem, NN layout. MODE 0: C = tf32(acc). MODE 2: resid+transp.
template<int MODE>
__global__ __launch_bounds__(512, 1) void gemm_tc(
    const float* __restrict__ A, int lda, long sA,
    const float* __restrict__ Bw, int ldb, long sB,
    float* __restrict__ C, long sC, int K,
    const float* __restrict__ resid)
{
    extern __shared__ float sm[];
    const int tid = threadIdx.x, lane = tid & 31, wid = tid >> 5;
    const int grp = lane >> 2, tg = lane & 3;
    const int wm = (wid & 1) * 64, wn = (wid >> 1) * 32;
    const int m0 = blockIdx.x * 128;
    const int z = blockIdx.y;
    A  += (long)z * sA;
    Bw += (long)z * sB;
    C  += (long)z * sC;

    float4 ra[2], rb[4];

    auto ldg = [&](int kc) {
        #pragma unroll
        for (int p = 0; p < 2; p++) {
            int idx = p * 512 + tid, row = idx >> 3, seg = idx & 7;
            ra[p] = *(const float4*)&A[(long)(m0 + row) * lda + kc * 32 + seg * 4];
        }
        #pragma unroll
        for (int p = 0; p < 4; p++) {
            int idx = p * 512 + tid, row = idx >> 6, seg = idx & 63;
            rb[p] = *(const float4*)&Bw[(long)(kc * 32 + row) * ldb + seg * 4];
        }
    };
    auto sts = [&](int stg) {
        float* As = sm + stg * G_STG;
        float* Bs = As + 4608;
        #pragma unroll
        for (int p = 0; p < 2; p++) {
            int idx = p * 512 + tid, row = idx >> 3, seg = idx & 7;
            *(float4*)&As[row * 36 + seg * 4] = ra[p];
        }
        #pragma unroll
        for (int p = 0; p < 4; p++) {
            int idx = p * 512 + tid, row = idx >> 6, seg = idx & 63;
            *(float4*)&Bs[row * 264 + seg * 4] = rb[p];
        }
    };

    float acc[4][4][4];
    #pragma unroll
    for (int i = 0; i < 4; i++)
        #pragma unroll
        for (int j = 0; j < 4; j++)
            #pragma unroll
            for (int r = 0; r < 4; r++) acc[i][j][r] = 0.f;

    const int nch = K >> 5;
    ldg(0); sts(0); __syncthreads();

    for (int ic = 0; ic < nch; ic++) {
        const int stg = ic & 1;
        if (ic + 1 < nch) ldg(ic + 1);

        const float* As = sm + stg * G_STG;
        const float* Bs = As + 4608;
        #pragma unroll
        for (int ks = 0; ks < 4; ks++) {
            const int k0 = ks * 8;
            unsigned af[4][4], bf[4][2];
            #pragma unroll
            for (int mi = 0; mi < 4; mi++) {
                int rm = wm + mi * 16;
                af[mi][0] = __float_as_uint(As[(rm + grp    ) * 36 + k0 + tg    ]);
                af[mi][1] = __float_as_uint(As[(rm + grp + 8) * 36 + k0 + tg    ]);
                af[mi][2] = __float_as_uint(As[(rm + grp    ) * 36 + k0 + tg + 4]);
                af[mi][3] = __float_as_uint(As[(rm + grp + 8) * 36 + k0 + tg + 4]);
            }
            #pragma unroll
            for (int ni = 0; ni < 4; ni++) {
                int cn = wn + ni * 8 + grp;
                bf[ni][0] = __float_as_uint(Bs[(k0 + tg    ) * 264 + cn]);
                bf[ni][1] = __float_as_uint(Bs[(k0 + tg + 4) * 264 + cn]);
            }
            #pragma unroll
            for (int mi = 0; mi < 4; mi++)
                #pragma unroll
                for (int ni = 0; ni < 4; ni++)
                    mma_tf32(acc[mi][ni], af[mi], bf[ni]);
        }
        if (ic + 1 < nch) { sts(stg ^ 1); __syncthreads(); }
    }

    #pragma unroll
    for (int mi = 0; mi < 4; mi++) {
        #pragma unroll
        for (int ni = 0; ni < 4; ni++) {
            int r0 = m0 + wm + mi * 16 + grp;
            int c0 = wn + ni * 8 + tg * 2;
            if (MODE == 0) {
                *(float2*)&C[(long)r0 * 256 + c0] =
                    make_float2(tf32r(acc[mi][ni][0]), tf32r(acc[mi][ni][1]));
                *(float2*)&C[(long)(r0 + 8) * 256 + c0] =
                    make_float2(tf32r(acc[mi][ni][2]), tf32r(acc[mi][ni][3]));
            } else {
                int bb = r0 / Ssz;
                int ss = r0 - bb * Ssz;
                long a0 = ((long)(bb * 256 + c0)) * Ssz + ss;
                C[a0          ] = resid[a0          ] + acc[mi][ni][0];
                C[a0 + Ssz    ] = resid[a0 + Ssz    ] + acc[mi][ni][1];
                C[a0 + 8      ] = resid[a0 + 8      ] + acc[mi][ni][2];
                C[a0 + Ssz + 8] = resid[a0 + Ssz + 8] + acc[mi][ni][3];
            }
        }
    }
}

// ---- scores: E[b,s,t] = exp(Q[b]·K[b]^T / 16), raw fp32 --------------------
// CTA 128s x 256t, 512 threads, 16 warps (2m x 8n), 8 batches looped in-CTA.
__global__ __launch_bounds__(512, 1) void tc_scores(
    const float* __restrict__ Q, const float* __restrict__ Ko,
    float* __restrict__ E)
{
    extern __shared__ float sm[];
    const int tid = threadIdx.x, lane = tid & 31, wid = tid >> 5;
    const int grp = lane >> 2, tg = lane & 3;
    const int wm = (wid & 1) * 64, wn = (wid >> 1) * 32;
    const int s0 = blockIdx.y * 128, t0 = blockIdx.x * 256;

    float4 ra[2], rk[4];

    auto ldg = [&](int it) {
        int b = it >> 3, kc = it & 7;
        const float* qa = Q  + ((long)b * Ssz + s0) * 256;
        const float* kb = Ko + ((long)b * Ssz + t0) * 256;
        #pragma unroll
        for (int p = 0; p < 2; p++) {
            int idx = p * 512 + tid, row = idx >> 3, seg = idx & 7;
            ra[p] = *(const float4*)&qa[(long)row * 256 + kc * 32 + seg * 4];
        }
        #pragma unroll
        for (int p = 0; p < 4; p++) {
            int idx = p * 512 + tid, row = idx >> 3, seg = idx & 7;
            rk[p] = *(const float4*)&kb[(long)row * 256 + kc * 32 + seg * 4];
        }
    };
    auto sts = [&](int stg) {
        float* Qs = sm + stg * S_STG;
        float* Ks = Qs + 4608;
        #pragma unroll
        for (int p = 0; p < 2; p++) {
            int idx = p * 512 + tid, row = idx >> 3, seg = idx & 7;
            *(float4*)&Qs[row * 36 + seg * 4] = ra[p];
        }
        #pragma unroll
        for (int p = 0; p < 4; p++) {
            int idx = p * 512 + tid, row = idx >> 3, seg = idx & 7;
            *(float4*)&Ks[row * 36 + seg * 4] = rk[p];
        }
    };

    float acc[4][4][4];
    ldg(0); sts(0); __syncthreads();

    for (int it = 0; it < 64; it++) {
        const int stg = it & 1;
        if (it + 1 < 64) ldg(it + 1);

        if ((it & 7) == 0) {
            #pragma unroll
            for (int i = 0; i < 4; i++)
                #pragma unroll
                for (int j = 0; j < 4; j++)
                    #pragma unroll
                    for (int r = 0; r < 4; r++) acc[i][j][r] = 0.f;
        }

        const float* Qs = sm + stg * S_STG;
        const float* Ks = Qs + 4608;
        #pragma unroll
        for (int ks = 0; ks < 4; ks++) {
            const int k0 = ks * 8;
            unsigned af[4][4], bf[4][2];
            #pragma unroll
            for (int mi = 0; mi < 4; mi++) {
                int rm = wm + mi * 16;
                af[mi][0] = __float_as_uint(Qs[(rm + grp    ) * 36 + k0 + tg    ]);
                af[mi][1] = __float_as_uint(Qs[(rm + grp + 8) * 36 + k0 + tg    ]);
                af[mi][2] = __float_as_uint(Qs[(rm + grp    ) * 36 + k0 + tg + 4]);
                af[mi][3] = __float_as_uint(Qs[(rm + grp + 8) * 36 + k0 + tg + 4]);
            }
            #pragma unroll
            for (int ni = 0; ni < 4; ni++) {
                int cn = wn + ni * 8 + grp;
                bf[ni][0] = __float_as_uint(Ks[cn * 36 + k0 + tg    ]);
                bf[ni][1] = __float_as_uint(Ks[cn * 36 + k0 + tg + 4]);
            }
            #pragma unroll
            for (int mi = 0; mi < 4; mi++)
                #pragma unroll
                for (int ni = 0; ni < 4; ni++)
                    mma_tf32(acc[mi][ni], af[mi], bf[ni]);
        }

        if ((it & 7) == 7) {
            const int b = it >> 3;
            float* Eb = E + (long)b * SSl;
            #pragma unroll
            for (int mi = 0; mi < 4; mi++) {
                #pragma unroll
                for (int ni = 0; ni < 4; ni++) {
                    int r0 = s0 + wm + mi * 16 + grp;
                    int c0 = t0 + wn + ni * 8 + tg * 2;
                    float e0 = __expf(acc[mi][ni][0] * 0.0625f);
                    float e1 = __expf(acc[mi][ni][1] * 0.0625f);
                    float e2 = __expf(acc[mi][ni][2] * 0.0625f);
                    float e3 = __expf(acc[mi][ni][3] * 0.0625f);
                    *(float2*)&Eb[(long)r0 * Ssz + c0] = make_float2(e0, e1);
                    *(float2*)&Eb[(long)(r0 + 8) * Ssz + c0] = make_float2(e2, e3);
                }
            }
        }
        if (it + 1 < 64) { sts(stg ^ 1); __syncthreads(); }
    }
}

// ---- normalize: E[b,s,t] *= 1/sum_b E[b,s,t], tf32-rounded in place --------
__global__ __launch_bounds__(256, 4) void normalize_kernel(float* __restrict__ E)
{
    long i = ((long)blockIdx.x * 256 + threadIdx.x) * 4;
    float4 e[Bbat];
    float4 s = make_float4(0.f, 0.f, 0.f, 0.f);
    #pragma unroll
    for (int b = 0; b < Bbat; b++) {
        e[b] = *(const float4*)&E[b * SSl + i];
        s.x += e[b].x; s.y += e[b].y; s.z += e[b].z; s.w += e[b].w;
    }
    float4 inv = make_float4(1.f / s.x, 1.f / s.y, 1.f / s.z, 1.f / s.w);
    #pragma unroll
    for (int b = 0; b < Bbat; b++) {
        *(float4*)&E[b * SSl + i] =
            make_float4(tf32r(e[b].x * inv.x), tf32r(e[b].y * inv.y),
                        tf32r(e[b].z * inv.z), tf32r(e[b].w * inv.w));
    }
}

// ---- launch ----------------------------------------------------------------
extern "C" void kernel_launch(void* const* d_in, const int* in_sizes, int n_in,
                              void* d_out, int out_size) {
    const float* x_l = (const float*)d_in[0];
    const float* x_r = (const float*)d_in[1];
    const float* Wq  = (const float*)d_in[2];
    const float* Wk  = (const float*)d_in[3];
    const float* Wv  = (const float*)d_in[4];
    const float* Wo  = (const float*)d_in[5];
    const float* g1  = (const float*)d_in[6];
    const float* b1  = (const float*)d_in[7];
    const float* g2  = (const float*)d_in[8];
    const float* b2  = (const float*)d_in[9];
    float* out = (float*)d_out;

    float *xln, *q, *k, *v, *E, *O, *Wt;
    cudaGetSymbolAddress((void**)&xln, g_xln);
    cudaGetSymbolAddress((void**)&q,   g_q);
    cudaGetSymbolAddress((void**)&k,   g_k);
    cudaGetSymbolAddress((void**)&v,   g_v);
    cudaGetSymbolAddress((void**)&E,   g_E);
    cudaGetSymbolAddress((void**)&O,   g_O);
    cudaGetSymbolAddress((void**)&Wt,  g_Wt);

    cudaFuncSetAttribute(gemm_tc<0>, cudaFuncAttributeMaxDynamicSharedMemorySize, SMEM_G);
    cudaFuncSetAttribute(gemm_tc<2>, cudaFuncAttributeMaxDynamicSharedMemorySize, SMEM_G);
    cudaFuncSetAttribute(tc_scores,  cudaFuncAttributeMaxDynamicSharedMemorySize, SMEM_S);

    wconv_kernel<<<256, 256>>>(Wq, Wk, Wv, Wo, Wt);
    ln_kernel<<<dim3(Ssz / 32, Bbat, 2), 256>>>(x_l, x_r, g1, b1, g2, b2,
                                                xln, xln + BSC);

    for (int s = 0; s < 2; s++) {
        gemm_tc<0><<<dim3(144, 1), 512, SMEM_G>>>(xln + s * BSC, 256, 0,
                                                  Wt + 0 * 65536, 256, 0,
                                                  q + s * BSC, 0, 256, nullptr);
        gemm_tc<0><<<dim3(144, 1), 512, SMEM_G>>>(xln + s * BSC, 256, 0,
                                                  Wt + 1 * 65536, 256, 0,
                                                  k + s * BSC, 0, 256, nullptr);
        gemm_tc<0><<<dim3(144, 1), 512, SMEM_G>>>(xln + s * BSC, 256, 0,
                                                  Wt + 2 * 65536, 256, 0,
                                                  v + s * BSC, 0, 256, nullptr);
    }

    for (int s = 0; s < 2; s++) {
        tc_scores<<<dim3(9, 18), 512, SMEM_S>>>(q + s * BSC, k + (1 - s) * BSC, E);
        normalize_kernel<<<(int)(SSl / 1024), 256>>>(E);
        gemm_tc<0><<<dim3(18, 8), 512, SMEM_G>>>(E, Ssz, SSl,
                                                 v + s * BSC, 256, (long)Ssz * 256,
                                                 O, (long)Ssz * 256, Ssz, nullptr);
        gemm_tc<2><<<dim3(144, 1), 512, SMEM_G>>>(O, 256, 0,
                                                  Wt + 3 * 65536, 256, 0,
                                                  out + s * BSC, 0, 256,
                                                  s ? x_r : x_l);
    }
}

// round 9
// speedup vs baseline: 1.6042x; 1.3632x over previous
#include <cuda_runtime.h>
#include <cuda_fp16.h>
#include <cstdint>

#define Ssz   2304
#define Csz   256
#define Bbat  8
#define BSC   (Bbat*Ssz*Csz)
#define SSl   ((long)Ssz*Ssz)

// ---- scratch (fp16 intermediates) ------------------------------------------
__device__ __half g_xln[2][BSC];
__device__ __half g_q[2][BSC];
__device__ __half g_k[2][BSC];
__device__ __half g_vt[2][BSC];          // V^T: [b][c][t]
__device__ __half g_E[(size_t)Bbat*Ssz*Ssz];
__device__ __half g_O[BSC];
__device__ __half g_Wt[4][Csz*Csz];      // W^T [n][k] fp16

// ---- helpers ---------------------------------------------------------------
__device__ __forceinline__ void mma_f16(float acc[4], const unsigned a[4], const unsigned b[2]) {
    asm volatile(
        "mma.sync.aligned.m16n8k16.row.col.f32.f16.f16.f32 "
        "{%0,%1,%2,%3}, {%4,%5,%6,%7}, {%8,%9}, {%0,%1,%2,%3};\n"
        : "+f"(acc[0]), "+f"(acc[1]), "+f"(acc[2]), "+f"(acc[3])
        : "r"(a[0]), "r"(a[1]), "r"(a[2]), "r"(a[3]), "r"(b[0]), "r"(b[1]));
}
// XOR-swizzled smem: rows of 32 halfs (64B), 16B segs swizzled by (r + r>>2)&3
__device__ __forceinline__ int swx(int r) { return (r + (r >> 2)) & 3; }
__device__ __forceinline__ unsigned lds32h(const char* base, int r, int w) {
    // w = 4B-word index 0..15 within row
    return *(const unsigned*)(base + r * 64 + (((w >> 2) ^ swx(r)) << 4) + (w & 3) * 4);
}
__device__ __forceinline__ void sts128h(char* base, int r, int s, uint4 v) {
    *(uint4*)(base + r * 64 + ((s ^ swx(r)) << 4)) = v;
}

// stage: A 128 rows x 64B = 8192 | B 256 rows x 64B = 16384 -> 24576 B
#define STG_B   24576
#define SMEM_GM 69632    // max(2 stages = 49152, V-transpose buf 256*136*2 = 69632)
#define SMEM_SC 49152

// ---- weight convert: W[k][n] fp32 -> Wt[n][k] fp16 -------------------------
__global__ void wconv_h(const float* __restrict__ wq, const float* __restrict__ wk,
                        const float* __restrict__ wv, const float* __restrict__ wo,
                        __half* __restrict__ wt) {
    int mat = blockIdx.y;
    const float* w = mat == 0 ? wq : mat == 1 ? wk : mat == 2 ? wv : wo;
    int k = blockIdx.x, n = threadIdx.x;
    wt[mat * 65536 + n * 256 + k] = __float2half_rn(w[k * 256 + n]);
}

// ---- LayerNorm over C + transpose [B,C,S]->[B,S,C], fp16 out ---------------
__global__ __launch_bounds__(256, 2) void ln_kernel(
    const float* __restrict__ xl, const float* __restrict__ xr,
    const float* __restrict__ g1, const float* __restrict__ b1,
    const float* __restrict__ g2, const float* __restrict__ b2,
    __half* __restrict__ xlnL, __half* __restrict__ xlnR)
{
    const int side = blockIdx.z;
    const float* x  = side ? xr : xl;
    const float* g  = side ? g2 : g1;
    const float* bb = side ? b2 : b1;
    __half* xo = side ? xlnR : xlnL;

    const int b  = blockIdx.y;
    const int s0 = blockIdx.x * 32;
    const int tid = threadIdx.x;
    const int tx = tid & 31, ty = tid >> 5;

    __shared__ float xs[256][33];
    __shared__ float ps[8][32], ps2[8][32];
    __shared__ float mu[32], rs[32];

    const float* xb = x + (size_t)b * Csz * Ssz;
    #pragma unroll
    for (int cc = 0; cc < 32; cc++) {
        int c = cc * 8 + ty;
        xs[c][tx] = xb[(size_t)c * Ssz + s0 + tx];
    }
    __syncthreads();

    float sum = 0.f, sq = 0.f;
    #pragma unroll
    for (int i = 0; i < 32; i++) {
        float v = xs[ty * 32 + i][tx];
        sum += v; sq += v * v;
    }
    ps[ty][tx] = sum; ps2[ty][tx] = sq;
    __syncthreads();

    if (ty == 0) {
        float s1 = 0.f, s2 = 0.f;
        #pragma unroll
        for (int j = 0; j < 8; j++) { s1 += ps[j][tx]; s2 += ps2[j][tx]; }
        float m = s1 * (1.f / 256.f);
        float v = s2 * (1.f / 256.f) - m * m;
        mu[tx] = m;
        rs[tx] = rsqrtf(v + 1e-5f);
    }
    __syncthreads();

    const float gc = g[tid], bc = bb[tid];
    __half* xob = xo + ((size_t)b * Ssz + s0) * Csz;
    #pragma unroll
    for (int si = 0; si < 32; si++)
        xob[si * Csz + tid] = __float2half_rn((xs[tid][si] - mu[si]) * rs[si] * gc + bc);
}

// ---- fp16 GEMM: C[M,256] = A[M,K] @ Bt[N=256,K]^T (NT, both k-contig) ------
// CTA 128x256, 512 thr, 16 warps (2m x 8n), warp 64x32, K-chunk 32, dbl-buffer.
// MODE 0: C fp16 [m][n].  MODE 1: Vt[(b*256+c)*S + s] fp16 via smem transpose.
// MODE 2: out fp32 [b][c][s] = resid + acc.
template<int MODE>
__global__ __launch_bounds__(512, 1) void gemm_h(
    const __half* __restrict__ A, int lda, long sA,
    const __half* __restrict__ Bt, int ldb, long sB,
    void* __restrict__ Cv, long sC, int K,
    const float* __restrict__ resid)
{
    extern __shared__ char smc[];
    const int tid = threadIdx.x, lane = tid & 31, wid = tid >> 5;
    const int grp = lane >> 2, tg = lane & 3;
    const int wm = (wid & 1) * 64, wn = (wid >> 1) * 32;
    const int m0 = blockIdx.x * 128;
    const int z = blockIdx.y;
    A  += (long)z * sA;
    Bt += (long)z * sB;

    const int ar = tid >> 2, as_ = tid & 3;     // A: 128 rows, 4 segs
    uint4 ra, rb[2];

    auto ldg = [&](int kc) {
        ra = *(const uint4*)&A[(long)(m0 + ar) * lda + kc * 32 + as_ * 8];
        #pragma unroll
        for (int p = 0; p < 2; p++) {
            int idx = p * 512 + tid, row = idx >> 2, sg = idx & 3;
            rb[p] = *(const uint4*)&Bt[(long)row * ldb + kc * 32 + sg * 8];
        }
    };
    auto sts = [&](int stg) {
        char* As = smc + stg * STG_B;
        char* Bs = As + 8192;
        sts128h(As, ar, as_, ra);
        #pragma unroll
        for (int p = 0; p < 2; p++) {
            int idx = p * 512 + tid, row = idx >> 2, sg = idx & 3;
            sts128h(Bs, row, sg, rb[p]);
        }
    };

    float acc[4][4][4];
    #pragma unroll
    for (int i = 0; i < 4; i++)
        #pragma unroll
        for (int j = 0; j < 4; j++)
            #pragma unroll
            for (int r = 0; r < 4; r++) acc[i][j][r] = 0.f;

    const int nch = K >> 5;
    ldg(0); sts(0); __syncthreads();

    for (int ic = 0; ic < nch; ic++) {
        const int stg = ic & 1;
        if (ic + 1 < nch) ldg(ic + 1);

        const char* As = smc + stg * STG_B;
        const char* Bs = As + 8192;
        #pragma unroll
        for (int ks = 0; ks < 2; ks++) {
            const int kw = ks * 8;
            unsigned af[4][4], bf[4][2];
            #pragma unroll
            for (int mi = 0; mi < 4; mi++) {
                int r1 = wm + mi * 16 + grp;
                af[mi][0] = lds32h(As, r1,     kw + tg);
                af[mi][1] = lds32h(As, r1 + 8, kw + tg);
                af[mi][2] = lds32h(As, r1,     kw + tg + 4);
                af[mi][3] = lds32h(As, r1 + 8, kw + tg + 4);
            }
            #pragma unroll
            for (int ni = 0; ni < 4; ni++) {
                int rn = wn + ni * 8 + grp;
                bf[ni][0] = lds32h(Bs, rn, kw + tg);
                bf[ni][1] = lds32h(Bs, rn, kw + tg + 4);
            }
            #pragma unroll
            for (int mi = 0; mi < 4; mi++)
                #pragma unroll
                for (int ni = 0; ni < 4; ni++)
                    mma_f16(acc[mi][ni], af[mi], bf[ni]);
        }
        if (ic + 1 < nch) { sts(stg ^ 1); __syncthreads(); }
    }

    if (MODE == 0) {
        __half* C = (__half*)Cv + (long)z * sC;
        #pragma unroll
        for (int mi = 0; mi < 4; mi++) {
            #pragma unroll
            for (int ni = 0; ni < 4; ni++) {
                int r0 = m0 + wm + mi * 16 + grp;
                int c0 = wn + ni * 8 + tg * 2;
                *(__half2*)&C[(long)r0 * 256 + c0] =
                    __floats2half2_rn(acc[mi][ni][0], acc[mi][ni][1]);
                *(__half2*)&C[(long)(r0 + 8) * 256 + c0] =
                    __floats2half2_rn(acc[mi][ni][2], acc[mi][ni][3]);
            }
        }
    } else if (MODE == 1) {
        __syncthreads();
        __half* tb = (__half*)smc;              // [256][136]
        #pragma unroll
        for (int mi = 0; mi < 4; mi++) {
            #pragma unroll
            for (int ni = 0; ni < 4; ni++) {
                int r  = wm + mi * 16 + grp;
                int c0 = wn + ni * 8 + tg * 2;
                tb[c0 * 136 + r]           = __float2half_rn(acc[mi][ni][0]);
                tb[(c0 + 1) * 136 + r]     = __float2half_rn(acc[mi][ni][1]);
                tb[c0 * 136 + r + 8]       = __float2half_rn(acc[mi][ni][2]);
                tb[(c0 + 1) * 136 + r + 8] = __float2half_rn(acc[mi][ni][3]);
            }
        }
        __syncthreads();
        const int bb = m0 / Ssz, s0m = m0 - bb * Ssz;
        __half* C = (__half*)Cv;
        #pragma unroll
        for (int p = 0; p < 8; p++) {
            int idx = p * 512 + tid;
            int c = idx >> 4, ms = idx & 15;
            uint4 v = *(uint4*)&tb[c * 136 + ms * 8];
            *(uint4*)&C[((long)(bb * 256 + c)) * Ssz + s0m + ms * 8] = v;
        }
    } else {
        float* C = (float*)Cv;
        #pragma unroll
        for (int mi = 0; mi < 4; mi++) {
            #pragma unroll
            for (int ni = 0; ni < 4; ni++) {
                int r0 = m0 + wm + mi * 16 + grp;
                int c0 = wn + ni * 8 + tg * 2;
                int bb = r0 / Ssz;
                int ss = r0 - bb * Ssz;
                long a0 = ((long)(bb * 256 + c0)) * Ssz + ss;
                C[a0          ] = resid[a0          ] + acc[mi][ni][0];
                C[a0 + Ssz    ] = resid[a0 + Ssz    ] + acc[mi][ni][1];
                C[a0 + 8      ] = resid[a0 + 8      ] + acc[mi][ni][2];
                C[a0 + Ssz + 8] = resid[a0 + Ssz + 8] + acc[mi][ni][3];
            }
        }
    }
}

// ---- scores: E[b,s,t] = exp(Q[b]·K[b]^T / 16) fp16, 8 batches per CTA ------
__global__ __launch_bounds__(512, 1) void sc_h(
    const __half* __restrict__ Q, const __half* __restrict__ Ko,
    __half* __restrict__ E)
{
    extern __shared__ char smc[];
    const int tid = threadIdx.x, lane = tid & 31, wid = tid >> 5;
    const int grp = lane >> 2, tg = lane & 3;
    const int wm = (wid & 1) * 64, wn = (wid >> 1) * 32;
    const int s0 = blockIdx.y * 128, t0 = blockIdx.x * 256;

    const int ar = tid >> 2, as_ = tid & 3;
    uint4 ra, rb[2];

    auto ldg = [&](int it) {
        int b = it >> 3, kc = it & 7;
        const __half* qa = Q  + ((long)b * Ssz + s0) * 256;
        const __half* kb = Ko + ((long)b * Ssz + t0) * 256;
        ra = *(const uint4*)&qa[(long)ar * 256 + kc * 32 + as_ * 8];
        #pragma unroll
        for (int p = 0; p < 2; p++) {
            int idx = p * 512 + tid, row = idx >> 2, sg = idx & 3;
            rb[p] = *(const uint4*)&kb[(long)row * 256 + kc * 32 + sg * 8];
        }
    };
    auto sts = [&](int stg) {
        char* As = smc + stg * STG_B;
        char* Bs = As + 8192;
        sts128h(As, ar, as_, ra);
        #pragma unroll
        for (int p = 0; p < 2; p++) {
            int idx = p * 512 + tid, row = idx >> 2, sg = idx & 3;
            sts128h(Bs, row, sg, rb[p]);
        }
    };

    float acc[4][4][4];
    ldg(0); sts(0); __syncthreads();

    for (int it = 0; it < 64; it++) {
        const int stg = it & 1;
        if (it + 1 < 64) ldg(it + 1);

        if ((it & 7) == 0) {
            #pragma unroll
            for (int i = 0; i < 4; i++)
                #pragma unroll
                for (int j = 0; j < 4; j++)
                    #pragma unroll
                    for (int r = 0; r < 4; r++) acc[i][j][r] = 0.f;
        }

        const char* As = smc + stg * STG_B;
        const char* Bs = As + 8192;
        #pragma unroll
        for (int ks = 0; ks < 2; ks++) {
            const int kw = ks * 8;
            unsigned af[4][4], bf[4][2];
            #pragma unroll
            for (int mi = 0; mi < 4; mi++) {
                int r1 = wm + mi * 16 + grp;
                af[mi][0] = lds32h(As, r1,     kw + tg);
                af[mi][1] = lds32h(As, r1 + 8, kw + tg);
                af[mi][2] = lds32h(As, r1,     kw + tg + 4);
                af[mi][3] = lds32h(As, r1 + 8, kw + tg + 4);
            }
            #pragma unroll
            for (int ni = 0; ni < 4; ni++) {
                int rn = wn + ni * 8 + grp;
                bf[ni][0] = lds32h(Bs, rn, kw + tg);
                bf[ni][1] = lds32h(Bs, rn, kw + tg + 4);
            }
            #pragma unroll
            for (int mi = 0; mi < 4; mi++)
                #pragma unroll
                for (int ni = 0; ni < 4; ni++)
                    mma_f16(acc[mi][ni], af[mi], bf[ni]);
        }

        if ((it & 7) == 7) {
            const int b = it >> 3;
            __half* Eb = E + (long)b * SSl;
            #pragma unroll
            for (int mi = 0; mi < 4; mi++) {
                #pragma unroll
                for (int ni = 0; ni < 4; ni++) {
                    int r0 = s0 + wm + mi * 16 + grp;
                    int c0 = t0 + wn + ni * 8 + tg * 2;
                    *(__half2*)&Eb[(long)r0 * Ssz + c0] =
                        __floats2half2_rn(__expf(acc[mi][ni][0] * 0.0625f),
                                          __expf(acc[mi][ni][1] * 0.0625f));
                    *(__half2*)&Eb[(long)(r0 + 8) * Ssz + c0] =
                        __floats2half2_rn(__expf(acc[mi][ni][2] * 0.0625f),
                                          __expf(acc[mi][ni][3] * 0.0625f));
                }
            }
        }
        if (it + 1 < 64) { sts(stg ^ 1); __syncthreads(); }
    }
}

// ---- normalize: E[b,s,t] /= sum_b E[b,s,t] (fp16 in place) -----------------
__global__ __launch_bounds__(256, 4) void normalize_h(__half* __restrict__ E)
{
    long i = ((long)blockIdx.x * 256 + threadIdx.x) * 8;
    uint4 ev[Bbat];
    float s[8] = {0.f, 0.f, 0.f, 0.f, 0.f, 0.f, 0.f, 0.f};
    #pragma unroll
    for (int b = 0; b < Bbat; b++) {
        ev[b] = *(const uint4*)&E[b * SSl + i];
        const __half2* h2 = (const __half2*)&ev[b];
        #pragma unroll
        for (int j = 0; j < 4; j++) {
            float2 f = __half22float2(h2[j]);
            s[2 * j] += f.x; s[2 * j + 1] += f.y;
        }
    }
    float inv[8];
    #pragma unroll
    for (int j = 0; j < 8; j++) inv[j] = 1.f / s[j];
    #pragma unroll
    for (int b = 0; b < Bbat; b++) {
        __half2* h2 = (__half2*)&ev[b];
        #pragma unroll
        for (int j = 0; j < 4; j++) {
            float2 f = __half22float2(h2[j]);
            h2[j] = __floats2half2_rn(f.x * inv[2 * j], f.y * inv[2 * j + 1]);
        }
        *(uint4*)&E[b * SSl + i] = ev[b];
    }
}

// ---- launch ----------------------------------------------------------------
extern "C" void kernel_launch(void* const* d_in, const int* in_sizes, int n_in,
                              void* d_out, int out_size) {
    const float* x_l = (const float*)d_in[0];
    const float* x_r = (const float*)d_in[1];
    const float* Wq  = (const float*)d_in[2];
    const float* Wk  = (const float*)d_in[3];
    const float* Wv  = (const float*)d_in[4];
    const float* Wo  = (const float*)d_in[5];
    const float* g1  = (const float*)d_in[6];
    const float* b1  = (const float*)d_in[7];
    const float* g2  = (const float*)d_in[8];
    const float* b2  = (const float*)d_in[9];
    float* out = (float*)d_out;

    __half *xln, *q, *k, *vt, *E, *O, *Wt;
    cudaGetSymbolAddress((void**)&xln, g_xln);
    cudaGetSymbolAddress((void**)&q,   g_q);
    cudaGetSymbolAddress((void**)&k,   g_k);
    cudaGetSymbolAddress((void**)&vt,  g_vt);
    cudaGetSymbolAddress((void**)&E,   g_E);
    cudaGetSymbolAddress((void**)&O,   g_O);
    cudaGetSymbolAddress((void**)&Wt,  g_Wt);

    cudaFuncSetAttribute(gemm_h<0>, cudaFuncAttributeMaxDynamicSharedMemorySize, SMEM_GM);
    cudaFuncSetAttribute(gemm_h<1>, cudaFuncAttributeMaxDynamicSharedMemorySize, SMEM_GM);
    cudaFuncSetAttribute(gemm_h<2>, cudaFuncAttributeMaxDynamicSharedMemorySize, SMEM_GM);
    cudaFuncSetAttribute(sc_h,      cudaFuncAttributeMaxDynamicSharedMemorySize, SMEM_SC);

    wconv_h<<<dim3(256, 4), 256>>>(Wq, Wk, Wv, Wo, Wt);
    ln_kernel<<<dim3(Ssz / 32, Bbat, 2), 256>>>(x_l, x_r, g1, b1, g2, b2,
                                                xln, xln + BSC);

    for (int s = 0; s < 2; s++) {
        gemm_h<0><<<dim3(144, 1), 512, SMEM_GM>>>(xln + s * BSC, 256, 0,
                                                  Wt + 0 * 65536, 256, 0,
                                                  q + s * BSC, 0, 256, nullptr);
        gemm_h<0><<<dim3(144, 1), 512, SMEM_GM>>>(xln + s * BSC, 256, 0,
                                                  Wt + 1 * 65536, 256, 0,
                                                  k + s * BSC, 0, 256, nullptr);
        gemm_h<1><<<dim3(144, 1), 512, SMEM_GM>>>(xln + s * BSC, 256, 0,
                                                  Wt + 2 * 65536, 256, 0,
                                                  vt + s * BSC, 0, 256, nullptr);
    }

    for (int s = 0; s < 2; s++) {
        sc_h<<<dim3(9, 18), 512, SMEM_SC>>>(q + s * BSC, k + (1 - s) * BSC, E);
        normalize_h<<<(int)(SSl / 2048), 256>>>(E);
        gemm_h<0><<<dim3(18, 8), 512, SMEM_GM>>>(E, Ssz, SSl,
                                                 vt + s * BSC, Ssz, (long)Csz * Ssz,
                                                 O, (long)Ssz * Csz, Ssz, nullptr);
        gemm_h<2><<<dim3(144, 1), 512, SMEM_GM>>>(O, 256, 0,
                                                  Wt + 3 * 65536, 256, 0,
                                                  out + s * BSC, 0, 256,
                                                  s ? x_r : x_l);
    }
}

// round 10
// speedup vs baseline: 1.8539x; 1.1557x over previous
#include <cuda_runtime.h>
#include <cuda_fp16.h>
#include <cstdint>

#define Ssz   2304
#define Csz   256
#define Bbat  8
#define BSC   (Bbat*Ssz*Csz)
#define SSl   ((long)Ssz*Ssz)

// ---- scratch (fp16 intermediates) ------------------------------------------
__device__ __half g_xln[2][BSC];
__device__ __half g_q[2][BSC];
__device__ __half g_k[2][BSC];
__device__ __half g_vt[2][BSC];          // V^T: [b][c][t]
__device__ __half g_E[(size_t)Bbat*Ssz*Ssz];
__device__ __half g_O[BSC];
__device__ __half g_Wt[4][Csz*Csz];      // W^T [n][k] fp16

// ---- helpers ---------------------------------------------------------------
__device__ __forceinline__ void mma_f16(float acc[4], const unsigned a[4], const unsigned b[2]) {
    asm volatile(
        "mma.sync.aligned.m16n8k16.row.col.f32.f16.f16.f32 "
        "{%0,%1,%2,%3}, {%4,%5,%6,%7}, {%8,%9}, {%0,%1,%2,%3};\n"
        : "+f"(acc[0]), "+f"(acc[1]), "+f"(acc[2]), "+f"(acc[3])
        : "r"(a[0]), "r"(a[1]), "r"(a[2]), "r"(a[3]), "r"(b[0]), "r"(b[1]));
}
__device__ __forceinline__ void ldsm4(unsigned &r0, unsigned &r1, unsigned &r2, unsigned &r3,
                                      unsigned addr) {
    asm volatile("ldmatrix.sync.aligned.m8n8.x4.shared.b16 {%0,%1,%2,%3}, [%4];"
        : "=r"(r0), "=r"(r1), "=r"(r2), "=r"(r3) : "r"(addr));
}
// XOR-swizzled smem: rows of 32 halfs (64B), 16B segs swizzled by (r + r>>2)&3
__device__ __forceinline__ int swx(int r) { return (r + (r >> 2)) & 3; }
__device__ __forceinline__ unsigned smaddr(unsigned base, int r, int seg) {
    return base + r * 64 + ((seg ^ swx(r)) << 4);
}
__device__ __forceinline__ void sts128h(char* base, int r, int s, uint4 v) {
    *(uint4*)(base + r * 64 + ((s ^ swx(r)) << 4)) = v;
}

// stage: A 128 rows x 64B = 8192 | B 256 rows x 64B = 16384 -> 24576 B
#define STG_B   24576
#define SMEM_GM 69632    // max(2 stages = 49152, V-transpose buf 256*136*2 = 69632)
#define SMEM_SC 49152

// ---- weight convert: W[k][n] fp32 -> Wt[n][k] fp16 -------------------------
__global__ void wconv_h(const float* __restrict__ wq, const float* __restrict__ wk,
                        const float* __restrict__ wv, const float* __restrict__ wo,
                        __half* __restrict__ wt) {
    int mat = blockIdx.y;
    const float* w = mat == 0 ? wq : mat == 1 ? wk : mat == 2 ? wv : wo;
    int k = blockIdx.x, n = threadIdx.x;
    wt[mat * 65536 + n * 256 + k] = __float2half_rn(w[k * 256 + n]);
}

// ---- LayerNorm over C + transpose [B,C,S]->[B,S,C], fp16 out ---------------
__global__ __launch_bounds__(256, 2) void ln_kernel(
    const float* __restrict__ xl, const float* __restrict__ xr,
    const float* __restrict__ g1, const float* __restrict__ b1,
    const float* __restrict__ g2, const float* __restrict__ b2,
    __half* __restrict__ xlnL, __half* __restrict__ xlnR)
{
    const int side = blockIdx.z;
    const float* x  = side ? xr : xl;
    const float* g  = side ? g2 : g1;
    const float* bb = side ? b2 : b1;
    __half* xo = side ? xlnR : xlnL;

    const int b  = blockIdx.y;
    const int s0 = blockIdx.x * 32;
    const int tid = threadIdx.x;
    const int tx = tid & 31, ty = tid >> 5;

    __shared__ float xs[256][33];
    __shared__ float ps[8][32], ps2[8][32];
    __shared__ float mu[32], rs[32];

    const float* xb = x + (size_t)b * Csz * Ssz;
    #pragma unroll
    for (int cc = 0; cc < 32; cc++) {
        int c = cc * 8 + ty;
        xs[c][tx] = xb[(size_t)c * Ssz + s0 + tx];
    }
    __syncthreads();

    float sum = 0.f, sq = 0.f;
    #pragma unroll
    for (int i = 0; i < 32; i++) {
        float v = xs[ty * 32 + i][tx];
        sum += v; sq += v * v;
    }
    ps[ty][tx] = sum; ps2[ty][tx] = sq;
    __syncthreads();

    if (ty == 0) {
        float s1 = 0.f, s2 = 0.f;
        #pragma unroll
        for (int j = 0; j < 8; j++) { s1 += ps[j][tx]; s2 += ps2[j][tx]; }
        float m = s1 * (1.f / 256.f);
        float v = s2 * (1.f / 256.f) - m * m;
        mu[tx] = m;
        rs[tx] = rsqrtf(v + 1e-5f);
    }
    __syncthreads();

    const float gc = g[tid], bc = bb[tid];
    __half* xob = xo + ((size_t)b * Ssz + s0) * Csz;
    #pragma unroll
    for (int si = 0; si < 32; si++)
        xob[si * Csz + tid] = __float2half_rn((xs[tid][si] - mu[si]) * rs[si] * gc + bc);
}

// ---- fp16 GEMM: C[M,256] = A[M,K] @ Bt[N=256,K]^T (NT, both k-contig) ------
// CTA 128x256, 512 thr, 16 warps (2m x 8n), warp 64x32, K-chunk 32, dbl-buffer.
// Fragment loads via ldmatrix.x4.  MODE 0: C fp16 [m][n].
// MODE 1: Vt[(b*256+c)*S + s] fp16 via smem transpose.  MODE 2: resid+transp fp32.
template<int MODE>
__global__ __launch_bounds__(512, 1) void gemm_h(
    const __half* __restrict__ A, int lda, long sA,
    const __half* __restrict__ Bt, int ldb, long sB,
    void* __restrict__ Cv, long sC, int K,
    const float* __restrict__ resid)
{
    extern __shared__ char smc[];
    const int tid = threadIdx.x, lane = tid & 31, wid = tid >> 5;
    const int grp = lane >> 2, tg = lane & 3;
    const int wm = (wid & 1) * 64, wn = (wid >> 1) * 32;
    const int m0 = blockIdx.x * 128;
    const int z = blockIdx.y;
    A  += (long)z * sA;
    Bt += (long)z * sB;

    const unsigned sbu = (unsigned)__cvta_generic_to_shared(smc);
    // ldmatrix lane geometry
    const int la  = lane & 7;
    const int lb8 = ((lane >> 3) & 1) * 8;   // A: +8 rows for tiles 1,3
    const int lc16 = lane >> 4;              // A: k-seg select for tiles 2,3
    const int arow0 = wm + la + lb8;
    const int brow0 = wn + la + (lane >> 4) * 8;
    const int bseg0 = (lane >> 3) & 1;

    const int ar = tid >> 2, as_ = tid & 3;
    uint4 ra, rb[2];

    auto ldg = [&](int kc) {
        ra = *(const uint4*)&A[(long)(m0 + ar) * lda + kc * 32 + as_ * 8];
        #pragma unroll
        for (int p = 0; p < 2; p++) {
            int idx = p * 512 + tid, row = idx >> 2, sg = idx & 3;
            rb[p] = *(const uint4*)&Bt[(long)row * ldb + kc * 32 + sg * 8];
        }
    };
    auto sts = [&](int stg) {
        char* As = smc + stg * STG_B;
        char* Bs = As + 8192;
        sts128h(As, ar, as_, ra);
        #pragma unroll
        for (int p = 0; p < 2; p++) {
            int idx = p * 512 + tid, row = idx >> 2, sg = idx & 3;
            sts128h(Bs, row, sg, rb[p]);
        }
    };

    float acc[4][4][4];
    #pragma unroll
    for (int i = 0; i < 4; i++)
        #pragma unroll
        for (int j = 0; j < 4; j++)
            #pragma unroll
            for (int r = 0; r < 4; r++) acc[i][j][r] = 0.f;

    const int nch = K >> 5;
    ldg(0); sts(0); __syncthreads();

    for (int ic = 0; ic < nch; ic++) {
        const int stg = ic & 1;
        if (ic + 1 < nch) ldg(ic + 1);

        const unsigned Asu = sbu + stg * STG_B;
        const unsigned Bsu = Asu + 8192;
        #pragma unroll
        for (int ks = 0; ks < 2; ks++) {
            const int s0seg = ks * 2;
            unsigned af[4][4], bf[4][2];
            #pragma unroll
            for (int mi = 0; mi < 4; mi++)
                ldsm4(af[mi][0], af[mi][1], af[mi][2], af[mi][3],
                      smaddr(Asu, arow0 + mi * 16, s0seg + lc16));
            #pragma unroll
            for (int np = 0; np < 2; np++)
                ldsm4(bf[2 * np][0], bf[2 * np][1], bf[2 * np + 1][0], bf[2 * np + 1][1],
                      smaddr(Bsu, brow0 + np * 16, s0seg + bseg0));
            #pragma unroll
            for (int mi = 0; mi < 4; mi++)
                #pragma unroll
                for (int ni = 0; ni < 4; ni++)
                    mma_f16(acc[mi][ni], af[mi], bf[ni]);
        }
        if (ic + 1 < nch) { sts(stg ^ 1); __syncthreads(); }
    }

    if (MODE == 0) {
        __half* C = (__half*)Cv + (long)z * sC;
        #pragma unroll
        for (int mi = 0; mi < 4; mi++) {
            #pragma unroll
            for (int ni = 0; ni < 4; ni++) {
                int r0 = m0 + wm + mi * 16 + grp;
                int c0 = wn + ni * 8 + tg * 2;
                *(__half2*)&C[(long)r0 * 256 + c0] =
                    __floats2half2_rn(acc[mi][ni][0], acc[mi][ni][1]);
                *(__half2*)&C[(long)(r0 + 8) * 256 + c0] =
                    __floats2half2_rn(acc[mi][ni][2], acc[mi][ni][3]);
            }
        }
    } else if (MODE == 1) {
        __syncthreads();
        __half* tb = (__half*)smc;              // [256][136]
        #pragma unroll
        for (int mi = 0; mi < 4; mi++) {
            #pragma unroll
            for (int ni = 0; ni < 4; ni++) {
                int r  = wm + mi * 16 + grp;
                int c0 = wn + ni * 8 + tg * 2;
                tb[c0 * 136 + r]           = __float2half_rn(acc[mi][ni][0]);
                tb[(c0 + 1) * 136 + r]     = __float2half_rn(acc[mi][ni][1]);
                tb[c0 * 136 + r + 8]       = __float2half_rn(acc[mi][ni][2]);
                tb[(c0 + 1) * 136 + r + 8] = __float2half_rn(acc[mi][ni][3]);
            }
        }
        __syncthreads();
        const int bb = m0 / Ssz, s0m = m0 - bb * Ssz;
        __half* C = (__half*)Cv;
        #pragma unroll
        for (int p = 0; p < 8; p++) {
            int idx = p * 512 + tid;
            int c = idx >> 4, ms = idx & 15;
            uint4 v = *(uint4*)&tb[c * 136 + ms * 8];
            *(uint4*)&C[((long)(bb * 256 + c)) * Ssz + s0m + ms * 8] = v;
        }
    } else {
        float* C = (float*)Cv;
        #pragma unroll
        for (int mi = 0; mi < 4; mi++) {
            #pragma unroll
            for (int ni = 0; ni < 4; ni++) {
                int r0 = m0 + wm + mi * 16 + grp;
                int c0 = wn + ni * 8 + tg * 2;
                int bb = r0 / Ssz;
                int ss = r0 - bb * Ssz;
                long a0 = ((long)(bb * 256 + c0)) * Ssz + ss;
                C[a0          ] = resid[a0          ] + acc[mi][ni][0];
                C[a0 + Ssz    ] = resid[a0 + Ssz    ] + acc[mi][ni][1];
                C[a0 + 8      ] = resid[a0 + 8      ] + acc[mi][ni][2];
                C[a0 + Ssz + 8] = resid[a0 + Ssz + 8] + acc[mi][ni][3];
            }
        }
    }
}

// ---- scores: E[b,s,t] = exp(Q[b]·K[b]^T / 16) fp16, 8 batches per CTA ------
__global__ __launch_bounds__(512, 1) void sc_h(
    const __half* __restrict__ Q, const __half* __restrict__ Ko,
    __half* __restrict__ E)
{
    extern __shared__ char smc[];
    const int tid = threadIdx.x, lane = tid & 31, wid = tid >> 5;
    const int grp = lane >> 2, tg = lane & 3;
    const int wm = (wid & 1) * 64, wn = (wid >> 1) * 32;
    const int s0 = blockIdx.y * 128, t0 = blockIdx.x * 256;

    const unsigned sbu = (unsigned)__cvta_generic_to_shared(smc);
    const int la  = lane & 7;
    const int lb8 = ((lane >> 3) & 1) * 8;
    const int lc16 = lane >> 4;
    const int arow0 = wm + la + lb8;
    const int brow0 = wn + la + (lane >> 4) * 8;
    const int bseg0 = (lane >> 3) & 1;

    const int ar = tid >> 2, as_ = tid & 3;
    uint4 ra, rb[2];

    auto ldg = [&](int it) {
        int b = it >> 3, kc = it & 7;
        const __half* qa = Q  + ((long)b * Ssz + s0) * 256;
        const __half* kb = Ko + ((long)b * Ssz + t0) * 256;
        ra = *(const uint4*)&qa[(long)ar * 256 + kc * 32 + as_ * 8];
        #pragma unroll
        for (int p = 0; p < 2; p++) {
            int idx = p * 512 + tid, row = idx >> 2, sg = idx & 3;
            rb[p] = *(const uint4*)&kb[(long)row * 256 + kc * 32 + sg * 8];
        }
    };
    auto sts = [&](int stg) {
        char* As = smc + stg * STG_B;
        char* Bs = As + 8192;
        sts128h(As, ar, as_, ra);
        #pragma unroll
        for (int p = 0; p < 2; p++) {
            int idx = p * 512 + tid, row = idx >> 2, sg = idx & 3;
            sts128h(Bs, row, sg, rb[p]);
        }
    };

    float acc[4][4][4];
    ldg(0); sts(0); __syncthreads();

    for (int it = 0; it < 64; it++) {
        const int stg = it & 1;
        if (it + 1 < 64) ldg(it + 1);

        if ((it & 7) == 0) {
            #pragma unroll
            for (int i = 0; i < 4; i++)
                #pragma unroll
                for (int j = 0; j < 4; j++)
                    #pragma unroll
                    for (int r = 0; r < 4; r++) acc[i][j][r] = 0.f;
        }

        const unsigned Asu = sbu + stg * STG_B;
        const unsigned Bsu = Asu + 8192;
        #pragma unroll
        for (int ks = 0; ks < 2; ks++) {
            const int s0seg = ks * 2;
            unsigned af[4][4], bf[4][2];
            #pragma unroll
            for (int mi = 0; mi < 4; mi++)
                ldsm4(af[mi][0], af[mi][1], af[mi][2], af[mi][3],
                      smaddr(Asu, arow0 + mi * 16, s0seg + lc16));
            #pragma unroll
            for (int np = 0; np < 2; np++)
                ldsm4(bf[2 * np][0], bf[2 * np][1], bf[2 * np + 1][0], bf[2 * np + 1][1],
                      smaddr(Bsu, brow0 + np * 16, s0seg + bseg0));
            #pragma unroll
            for (int mi = 0; mi < 4; mi++)
                #pragma unroll
                for (int ni = 0; ni < 4; ni++)
                    mma_f16(acc[mi][ni], af[mi], bf[ni]);
        }

        if ((it & 7) == 7) {
            const int b = it >> 3;
            __half* Eb = E + (long)b * SSl;
            #pragma unroll
            for (int mi = 0; mi < 4; mi++) {
                #pragma unroll
                for (int ni = 0; ni < 4; ni++) {
                    int r0 = s0 + wm + mi * 16 + grp;
                    int c0 = t0 + wn + ni * 8 + tg * 2;
                    *(__half2*)&Eb[(long)r0 * Ssz + c0] =
                        __floats2half2_rn(__expf(acc[mi][ni][0] * 0.0625f),
                                          __expf(acc[mi][ni][1] * 0.0625f));
                    *(__half2*)&Eb[(long)(r0 + 8) * Ssz + c0] =
                        __floats2half2_rn(__expf(acc[mi][ni][2] * 0.0625f),
                                          __expf(acc[mi][ni][3] * 0.0625f));
                }
            }
        }
        if (it + 1 < 64) { sts(stg ^ 1); __syncthreads(); }
    }
}

// ---- normalize: E[b,s,t] /= sum_b E[b,s,t] (fp16 in place) -----------------
__global__ __launch_bounds__(256, 4) void normalize_h(__half* __restrict__ E)
{
    long i = ((long)blockIdx.x * 256 + threadIdx.x) * 8;
    uint4 ev[Bbat];
    float s[8] = {0.f, 0.f, 0.f, 0.f, 0.f, 0.f, 0.f, 0.f};
    #pragma unroll
    for (int b = 0; b < Bbat; b++) {
        ev[b] = *(const uint4*)&E[b * SSl + i];
        const __half2* h2 = (const __half2*)&ev[b];
        #pragma unroll
        for (int j = 0; j < 4; j++) {
            float2 f = __half22float2(h2[j]);
            s[2 * j] += f.x; s[2 * j + 1] += f.y;
        }
    }
    float inv[8];
    #pragma unroll
    for (int j = 0; j < 8; j++) inv[j] = 1.f / s[j];
    #pragma unroll
    for (int b = 0; b < Bbat; b++) {
        __half2* h2 = (__half2*)&ev[b];
        #pragma unroll
        for (int j = 0; j < 4; j++) {
            float2 f = __half22float2(h2[j]);
            h2[j] = __floats2half2_rn(f.x * inv[2 * j], f.y * inv[2 * j + 1]);
        }
        *(uint4*)&E[b * SSl + i] = ev[b];
    }
}

// ---- launch ----------------------------------------------------------------
extern "C" void kernel_launch(void* const* d_in, const int* in_sizes, int n_in,
                              void* d_out, int out_size) {
    const float* x_l = (const float*)d_in[0];
    const float* x_r = (const float*)d_in[1];
    const float* Wq  = (const float*)d_in[2];
    const float* Wk  = (const float*)d_in[3];
    const float* Wv  = (const float*)d_in[4];
    const float* Wo  = (const float*)d_in[5];
    const float* g1  = (const float*)d_in[6];
    const float* b1  = (const float*)d_in[7];
    const float* g2  = (const float*)d_in[8];
    const float* b2  = (const float*)d_in[9];
    float* out = (float*)d_out;

    __half *xln, *q, *k, *vt, *E, *O, *Wt;
    cudaGetSymbolAddress((void**)&xln, g_xln);
    cudaGetSymbolAddress((void**)&q,   g_q);
    cudaGetSymbolAddress((void**)&k,   g_k);
    cudaGetSymbolAddress((void**)&vt,  g_vt);
    cudaGetSymbolAddress((void**)&E,   g_E);
    cudaGetSymbolAddress((void**)&O,   g_O);
    cudaGetSymbolAddress((void**)&Wt,  g_Wt);

    cudaFuncSetAttribute(gemm_h<0>, cudaFuncAttributeMaxDynamicSharedMemorySize, SMEM_GM);
    cudaFuncSetAttribute(gemm_h<1>, cudaFuncAttributeMaxDynamicSharedMemorySize, SMEM_GM);
    cudaFuncSetAttribute(gemm_h<2>, cudaFuncAttributeMaxDynamicSharedMemorySize, SMEM_GM);
    cudaFuncSetAttribute(sc_h,      cudaFuncAttributeMaxDynamicSharedMemorySize, SMEM_SC);

    wconv_h<<<dim3(256, 4), 256>>>(Wq, Wk, Wv, Wo, Wt);
    ln_kernel<<<dim3(Ssz / 32, Bbat, 2), 256>>>(x_l, x_r, g1, b1, g2, b2,
                                                xln, xln + BSC);

    for (int s = 0; s < 2; s++) {
        gemm_h<0><<<dim3(144, 1), 512, SMEM_GM>>>(xln + s * BSC, 256, 0,
                                                  Wt + 0 * 65536, 256, 0,
                                                  q + s * BSC, 0, 256, nullptr);
        gemm_h<0><<<dim3(144, 1), 512, SMEM_GM>>>(xln + s * BSC, 256, 0,
                                                  Wt + 1 * 65536, 256, 0,
                                                  k + s * BSC, 0, 256, nullptr);
        gemm_h<1><<<dim3(144, 1), 512, SMEM_GM>>>(xln + s * BSC, 256, 0,
                                                  Wt + 2 * 65536, 256, 0,
                                                  vt + s * BSC, 0, 256, nullptr);
    }

    for (int s = 0; s < 2; s++) {
        sc_h<<<dim3(9, 18), 512, SMEM_SC>>>(q + s * BSC, k + (1 - s) * BSC, E);
        normalize_h<<<(int)(SSl / 2048), 256>>>(E);
        gemm_h<0><<<dim3(18, 8), 512, SMEM_GM>>>(E, Ssz, SSl,
                                                 vt + s * BSC, Ssz, (long)Csz * Ssz,
                                                 O, (long)Ssz * Csz, Ssz, nullptr);
        gemm_h<2><<<dim3(144, 1), 512, SMEM_GM>>>(O, 256, 0,
                                                  Wt + 3 * 65536, 256, 0,
                                                  out + s * BSC, 0, 256,
                                                  s ? x_r : x_l);
    }
}

// round 11
// speedup vs baseline: 1.9196x; 1.0354x over previous
#include <cuda_runtime.h>
#include <cuda_fp16.h>
#include <cstdint>

#define Ssz   2304
#define Csz   256
#define Bbat  8
#define BSC   (Bbat*Ssz*Csz)
#define SSl   ((long)Ssz*Ssz)

// ---- scratch (fp16 intermediates) ------------------------------------------
__device__ __half g_xln[2][BSC];
__device__ __half g_q[2][BSC];
__device__ __half g_k[2][BSC];
__device__ __half g_vt[2][BSC];          // V^T: [b][c][t]
__device__ __half g_E[(size_t)Bbat*Ssz*Ssz];
__device__ __half g_O[BSC];
__device__ __half g_Wt[4][Csz*Csz];      // W^T [n][k] fp16

// ---- helpers ---------------------------------------------------------------
__device__ __forceinline__ void mma_f16(float acc[4], const unsigned a[4], const unsigned b[2]) {
    asm volatile(
        "mma.sync.aligned.m16n8k16.row.col.f32.f16.f16.f32 "
        "{%0,%1,%2,%3}, {%4,%5,%6,%7}, {%8,%9}, {%0,%1,%2,%3};\n"
        : "+f"(acc[0]), "+f"(acc[1]), "+f"(acc[2]), "+f"(acc[3])
        : "r"(a[0]), "r"(a[1]), "r"(a[2]), "r"(a[3]), "r"(b[0]), "r"(b[1]));
}
__device__ __forceinline__ void ldsm4(unsigned &r0, unsigned &r1, unsigned &r2, unsigned &r3,
                                      unsigned addr) {
    asm volatile("ldmatrix.sync.aligned.m8n8.x4.shared.b16 {%0,%1,%2,%3}, [%4];"
        : "=r"(r0), "=r"(r1), "=r"(r2), "=r"(r3) : "r"(addr));
}
// XOR-swizzled smem: rows of 32 halfs (64B), 16B segs swizzled by (r + r>>2)&3
__device__ __forceinline__ int swx(int r) { return (r + (r >> 2)) & 3; }
__device__ __forceinline__ unsigned smaddr(unsigned base, int r, int seg) {
    return base + r * 64 + ((seg ^ swx(r)) << 4);
}
__device__ __forceinline__ void sts128h(char* base, int r, int s, uint4 v) {
    *(uint4*)(base + r * 64 + ((s ^ swx(r)) << 4)) = v;
}

// stage: A 128 rows x 64B = 8192 | B 256 rows x 64B = 16384 -> 24576 B
#define STG_B   24576
#define SMEM_GM 69632    // max(2 stages = 49152, V-transpose buf 256*136*2 = 69632)
#define SMEM_SC 49152

// ---- weight convert: W[k][n] fp32 -> Wt[n][k] fp16 -------------------------
__global__ void wconv_h(const float* __restrict__ wq, const float* __restrict__ wk,
                        const float* __restrict__ wv, const float* __restrict__ wo,
                        __half* __restrict__ wt) {
    int mat = blockIdx.y;
    const float* w = mat == 0 ? wq : mat == 1 ? wk : mat == 2 ? wv : wo;
    int k = blockIdx.x, n = threadIdx.x;
    wt[mat * 65536 + n * 256 + k] = __float2half_rn(w[k * 256 + n]);
}

// ---- LayerNorm over C + transpose [B,C,S]->[B,S,C], fp16 out ---------------
__global__ __launch_bounds__(256, 2) void ln_kernel(
    const float* __restrict__ xl, const float* __restrict__ xr,
    const float* __restrict__ g1, const float* __restrict__ b1,
    const float* __restrict__ g2, const float* __restrict__ b2,
    __half* __restrict__ xlnL, __half* __restrict__ xlnR)
{
    const int side = blockIdx.z;
    const float* x  = side ? xr : xl;
    const float* g  = side ? g2 : g1;
    const float* bb = side ? b2 : b1;
    __half* xo = side ? xlnR : xlnL;

    const int b  = blockIdx.y;
    const int s0 = blockIdx.x * 32;
    const int tid = threadIdx.x;
    const int tx = tid & 31, ty = tid >> 5;

    __shared__ float xs[256][33];
    __shared__ float ps[8][32], ps2[8][32];
    __shared__ float mu[32], rs[32];

    const float* xb = x + (size_t)b * Csz * Ssz;
    #pragma unroll
    for (int cc = 0; cc < 32; cc++) {
        int c = cc * 8 + ty;
        xs[c][tx] = xb[(size_t)c * Ssz + s0 + tx];
    }
    __syncthreads();

    float sum = 0.f, sq = 0.f;
    #pragma unroll
    for (int i = 0; i < 32; i++) {
        float v = xs[ty * 32 + i][tx];
        sum += v; sq += v * v;
    }
    ps[ty][tx] = sum; ps2[ty][tx] = sq;
    __syncthreads();

    if (ty == 0) {
        float s1 = 0.f, s2 = 0.f;
        #pragma unroll
        for (int j = 0; j < 8; j++) { s1 += ps[j][tx]; s2 += ps2[j][tx]; }
        float m = s1 * (1.f / 256.f);
        float v = s2 * (1.f / 256.f) - m * m;
        mu[tx] = m;
        rs[tx] = rsqrtf(v + 1e-5f);
    }
    __syncthreads();

    const float gc = g[tid], bc = bb[tid];
    __half* xob = xo + ((size_t)b * Ssz + s0) * Csz;
    #pragma unroll
    for (int si = 0; si < 32; si++)
        xob[si * Csz + tid] = __float2half_rn((xs[tid][si] - mu[si]) * rs[si] * gc + bc);
}

// ---- fp16 GEMM: C[M,256] = A[M,K] @ Bt[N=256,K]^T (NT, both k-contig) ------
// CTA 128x256, 256 thr, 8 warps (2m x 4n), warp tile 64x64, K-chunk 32,
// double-buffered, fragment loads via ldmatrix.x4.
// MODE 0: C fp16 [m][n].  MODE 1: Vt via smem transpose.  MODE 2: resid fp32.
template<int MODE>
__global__ __launch_bounds__(256, 1) void gemm_h(
    const __half* __restrict__ A, int lda, long sA,
    const __half* __restrict__ Bt, int ldb, long sB,
    void* __restrict__ Cv, long sC, int K,
    const float* __restrict__ resid)
{
    extern __shared__ char smc[];
    const int tid = threadIdx.x, lane = tid & 31, wid = tid >> 5;
    const int grp = lane >> 2, tg = lane & 3;
    const int wm = (wid & 1) * 64, wn = (wid >> 1) * 64;
    const int m0 = blockIdx.x * 128;
    const int z = blockIdx.y;
    A  += (long)z * sA;
    Bt += (long)z * sB;

    const unsigned sbu = (unsigned)__cvta_generic_to_shared(smc);
    // ldmatrix lane geometry
    const int la  = lane & 7;
    const int lb8 = ((lane >> 3) & 1) * 8;
    const int lc16 = lane >> 4;
    const int arow0 = wm + la + lb8;
    const int brow0 = wn + la + (lane >> 4) * 8;
    const int bseg0 = (lane >> 3) & 1;

    uint4 ra[2], rb[4];

    auto ldg = [&](int kc) {
        #pragma unroll
        for (int p = 0; p < 2; p++) {
            int idx = p * 256 + tid, row = idx >> 2, sg = idx & 3;
            ra[p] = *(const uint4*)&A[(long)(m0 + row) * lda + kc * 32 + sg * 8];
        }
        #pragma unroll
        for (int p = 0; p < 4; p++) {
            int idx = p * 256 + tid, row = idx >> 2, sg = idx & 3;
            rb[p] = *(const uint4*)&Bt[(long)row * ldb + kc * 32 + sg * 8];
        }
    };
    auto sts = [&](int stg) {
        char* As = smc + stg * STG_B;
        char* Bs = As + 8192;
        #pragma unroll
        for (int p = 0; p < 2; p++) {
            int idx = p * 256 + tid, row = idx >> 2, sg = idx & 3;
            sts128h(As, row, sg, ra[p]);
        }
        #pragma unroll
        for (int p = 0; p < 4; p++) {
            int idx = p * 256 + tid, row = idx >> 2, sg = idx & 3;
            sts128h(Bs, row, sg, rb[p]);
        }
    };

    float acc[4][8][4];
    #pragma unroll
    for (int i = 0; i < 4; i++)
        #pragma unroll
        for (int j = 0; j < 8; j++)
            #pragma unroll
            for (int r = 0; r < 4; r++) acc[i][j][r] = 0.f;

    const int nch = K >> 5;
    ldg(0); sts(0); __syncthreads();

    for (int ic = 0; ic < nch; ic++) {
        const int stg = ic & 1;
        if (ic + 1 < nch) ldg(ic + 1);

        const unsigned Asu = sbu + stg * STG_B;
        const unsigned Bsu = Asu + 8192;
        #pragma unroll
        for (int ks = 0; ks < 2; ks++) {
            const int s0seg = ks * 2;
            unsigned af[4][4], bf[8][2];
            #pragma unroll
            for (int mi = 0; mi < 4; mi++)
                ldsm4(af[mi][0], af[mi][1], af[mi][2], af[mi][3],
                      smaddr(Asu, arow0 + mi * 16, s0seg + lc16));
            #pragma unroll
            for (int np = 0; np < 4; np++)
                ldsm4(bf[2 * np][0], bf[2 * np][1], bf[2 * np + 1][0], bf[2 * np + 1][1],
                      smaddr(Bsu, brow0 + np * 16, s0seg + bseg0));
            #pragma unroll
            for (int mi = 0; mi < 4; mi++)
                #pragma unroll
                for (int ni = 0; ni < 8; ni++)
                    mma_f16(acc[mi][ni], af[mi], bf[ni]);
        }
        if (ic + 1 < nch) { sts(stg ^ 1); __syncthreads(); }
    }

    if (MODE == 0) {
        __half* C = (__half*)Cv + (long)z * sC;
        #pragma unroll
        for (int mi = 0; mi < 4; mi++) {
            #pragma unroll
            for (int ni = 0; ni < 8; ni++) {
                int r0 = m0 + wm + mi * 16 + grp;
                int c0 = wn + ni * 8 + tg * 2;
                *(__half2*)&C[(long)r0 * 256 + c0] =
                    __floats2half2_rn(acc[mi][ni][0], acc[mi][ni][1]);
                *(__half2*)&C[(long)(r0 + 8) * 256 + c0] =
                    __floats2half2_rn(acc[mi][ni][2], acc[mi][ni][3]);
            }
        }
    } else if (MODE == 1) {
        __syncthreads();
        __half* tb = (__half*)smc;              // [256][136]
        #pragma unroll
        for (int mi = 0; mi < 4; mi++) {
            #pragma unroll
            for (int ni = 0; ni < 8; ni++) {
                int r  = wm + mi * 16 + grp;
                int c0 = wn + ni * 8 + tg * 2;
                tb[c0 * 136 + r]           = __float2half_rn(acc[mi][ni][0]);
                tb[(c0 + 1) * 136 + r]     = __float2half_rn(acc[mi][ni][1]);
                tb[c0 * 136 + r + 8]       = __float2half_rn(acc[mi][ni][2]);
                tb[(c0 + 1) * 136 + r + 8] = __float2half_rn(acc[mi][ni][3]);
            }
        }
        __syncthreads();
        const int bb = m0 / Ssz, s0m = m0 - bb * Ssz;
        __half* C = (__half*)Cv;
        #pragma unroll
        for (int p = 0; p < 16; p++) {
            int idx = p * 256 + tid;
            int c = idx >> 4, ms = idx & 15;
            uint4 v = *(uint4*)&tb[c * 136 + ms * 8];
            *(uint4*)&C[((long)(bb * 256 + c)) * Ssz + s0m + ms * 8] = v;
        }
    } else {
        float* C = (float*)Cv;
        #pragma unroll
        for (int mi = 0; mi < 4; mi++) {
            #pragma unroll
            for (int ni = 0; ni < 8; ni++) {
                int r0 = m0 + wm + mi * 16 + grp;
                int c0 = wn + ni * 8 + tg * 2;
                int bb = r0 / Ssz;
                int ss = r0 - bb * Ssz;
                long a0 = ((long)(bb * 256 + c0)) * Ssz + ss;
                C[a0          ] = resid[a0          ] + acc[mi][ni][0];
                C[a0 + Ssz    ] = resid[a0 + Ssz    ] + acc[mi][ni][1];
                C[a0 + 8      ] = resid[a0 + 8      ] + acc[mi][ni][2];
                C[a0 + Ssz + 8] = resid[a0 + Ssz + 8] + acc[mi][ni][3];
            }
        }
    }
}

// ---- scores: E[b,s,t] = exp(Q[b]·K[b]^T / 16) fp16, 8 batches per CTA ------
// CTA 128s x 256t, 256 thr, 8 warps (2m x 4n), warp tile 64x64.
__global__ __launch_bounds__(256, 1) void sc_h(
    const __half* __restrict__ Q, const __half* __restrict__ Ko,
    __half* __restrict__ E)
{
    extern __shared__ char smc[];
    const int tid = threadIdx.x, lane = tid & 31, wid = tid >> 5;
    const int grp = lane >> 2, tg = lane & 3;
    const int wm = (wid & 1) * 64, wn = (wid >> 1) * 64;
    const int s0 = blockIdx.y * 128, t0 = blockIdx.x * 256;

    const unsigned sbu = (unsigned)__cvta_generic_to_shared(smc);
    const int la  = lane & 7;
    const int lb8 = ((lane >> 3) & 1) * 8;
    const int lc16 = lane >> 4;
    const int arow0 = wm + la + lb8;
    const int brow0 = wn + la + (lane >> 4) * 8;
    const int bseg0 = (lane >> 3) & 1;

    uint4 ra[2], rb[4];

    auto ldg = [&](int it) {
        int b = it >> 3, kc = it & 7;
        const __half* qa = Q  + ((long)b * Ssz + s0) * 256;
        const __half* kb = Ko + ((long)b * Ssz + t0) * 256;
        #pragma unroll
        for (int p = 0; p < 2; p++) {
            int idx = p * 256 + tid, row = idx >> 2, sg = idx & 3;
            ra[p] = *(const uint4*)&qa[(long)row * 256 + kc * 32 + sg * 8];
        }
        #pragma unroll
        for (int p = 0; p < 4; p++) {
            int idx = p * 256 + tid, row = idx >> 2, sg = idx & 3;
            rb[p] = *(const uint4*)&kb[(long)row * 256 + kc * 32 + sg * 8];
        }
    };
    auto sts = [&](int stg) {
        char* As = smc + stg * STG_B;
        char* Bs = As + 8192;
        #pragma unroll
        for (int p = 0; p < 2; p++) {
            int idx = p * 256 + tid, row = idx >> 2, sg = idx & 3;
            sts128h(As, row, sg, ra[p]);
        }
        #pragma unroll
        for (int p = 0; p < 4; p++) {
            int idx = p * 256 + tid, row = idx >> 2, sg = idx & 3;
            sts128h(Bs, row, sg, rb[p]);
        }
    };

    float acc[4][8][4];
    ldg(0); sts(0); __syncthreads();

    for (int it = 0; it < 64; it++) {
        const int stg = it & 1;
        if (it + 1 < 64) ldg(it + 1);

        if ((it & 7) == 0) {
            #pragma unroll
            for (int i = 0; i < 4; i++)
                #pragma unroll
                for (int j = 0; j < 8; j++)
                    #pragma unroll
                    for (int r = 0; r < 4; r++) acc[i][j][r] = 0.f;
        }

        const unsigned Asu = sbu + stg * STG_B;
        const unsigned Bsu = Asu + 8192;
        #pragma unroll
        for (int ks = 0; ks < 2; ks++) {
            const int s0seg = ks * 2;
            unsigned af[4][4], bf[8][2];
            #pragma unroll
            for (int mi = 0; mi < 4; mi++)
                ldsm4(af[mi][0], af[mi][1], af[mi][2], af[mi][3],
                      smaddr(Asu, arow0 + mi * 16, s0seg + lc16));
            #pragma unroll
            for (int np = 0; np < 4; np++)
                ldsm4(bf[2 * np][0], bf[2 * np][1], bf[2 * np + 1][0], bf[2 * np + 1][1],
                      smaddr(Bsu, brow0 + np * 16, s0seg + bseg0));
            #pragma unroll
            for (int mi = 0; mi < 4; mi++)
                #pragma unroll
                for (int ni = 0; ni < 8; ni++)
                    mma_f16(acc[mi][ni], af[mi], bf[ni]);
        }

        if ((it & 7) == 7) {
            const int b = it >> 3;
            __half* Eb = E + (long)b * SSl;
            #pragma unroll
            for (int mi = 0; mi < 4; mi++) {
                #pragma unroll
                for (int ni = 0; ni < 8; ni++) {
                    int r0 = s0 + wm + mi * 16 + grp;
                    int c0 = t0 + wn + ni * 8 + tg * 2;
                    *(__half2*)&Eb[(long)r0 * Ssz + c0] =
                        __floats2half2_rn(__expf(acc[mi][ni][0] * 0.0625f),
                                          __expf(acc[mi][ni][1] * 0.0625f));
                    *(__half2*)&Eb[(long)(r0 + 8) * Ssz + c0] =
                        __floats2half2_rn(__expf(acc[mi][ni][2] * 0.0625f),
                                          __expf(acc[mi][ni][3] * 0.0625f));
                }
            }
        }
        if (it + 1 < 64) { sts(stg ^ 1); __syncthreads(); }
    }
}

// ---- normalize: E[b,s,t] /= sum_b E[b,s,t] (fp16 in place) -----------------
__global__ __launch_bounds__(256, 4) void normalize_h(__half* __restrict__ E)
{
    long i = ((long)blockIdx.x * 256 + threadIdx.x) * 8;
    uint4 ev[Bbat];
    float s[8] = {0.f, 0.f, 0.f, 0.f, 0.f, 0.f, 0.f, 0.f};
    #pragma unroll
    for (int b = 0; b < Bbat; b++) {
        ev[b] = *(const uint4*)&E[b * SSl + i];
        const __half2* h2 = (const __half2*)&ev[b];
        #pragma unroll
        for (int j = 0; j < 4; j++) {
            float2 f = __half22float2(h2[j]);
            s[2 * j] += f.x; s[2 * j + 1] += f.y;
        }
    }
    float inv[8];
    #pragma unroll
    for (int j = 0; j < 8; j++) inv[j] = 1.f / s[j];
    #pragma unroll
    for (int b = 0; b < Bbat; b++) {
        __half2* h2 = (__half2*)&ev[b];
        #pragma unroll
        for (int j = 0; j < 4; j++) {
            float2 f = __half22float2(h2[j]);
            h2[j] = __floats2half2_rn(f.x * inv[2 * j], f.y * inv[2 * j + 1]);
        }
        *(uint4*)&E[b * SSl + i] = ev[b];
    }
}

// ---- launch ----------------------------------------------------------------
extern "C" void kernel_launch(void* const* d_in, const int* in_sizes, int n_in,
                              void* d_out, int out_size) {
    const float* x_l = (const float*)d_in[0];
    const float* x_r = (const float*)d_in[1];
    const float* Wq  = (const float*)d_in[2];
    const float* Wk  = (const float*)d_in[3];
    const float* Wv  = (const float*)d_in[4];
    const float* Wo  = (const float*)d_in[5];
    const float* g1  = (const float*)d_in[6];
    const float* b1  = (const float*)d_in[7];
    const float* g2  = (const float*)d_in[8];
    const float* b2  = (const float*)d_in[9];
    float* out = (float*)d_out;

    __half *xln, *q, *k, *vt, *E, *O, *Wt;
    cudaGetSymbolAddress((void**)&xln, g_xln);
    cudaGetSymbolAddress((void**)&q,   g_q);
    cudaGetSymbolAddress((void**)&k,   g_k);
    cudaGetSymbolAddress((void**)&vt,  g_vt);
    cudaGetSymbolAddress((void**)&E,   g_E);
    cudaGetSymbolAddress((void**)&O,   g_O);
    cudaGetSymbolAddress((void**)&Wt,  g_Wt);

    cudaFuncSetAttribute(gemm_h<0>, cudaFuncAttributeMaxDynamicSharedMemorySize, SMEM_GM);
    cudaFuncSetAttribute(gemm_h<1>, cudaFuncAttributeMaxDynamicSharedMemorySize, SMEM_GM);
    cudaFuncSetAttribute(gemm_h<2>, cudaFuncAttributeMaxDynamicSharedMemorySize, SMEM_GM);
    cudaFuncSetAttribute(sc_h,      cudaFuncAttributeMaxDynamicSharedMemorySize, SMEM_SC);

    wconv_h<<<dim3(256, 4), 256>>>(Wq, Wk, Wv, Wo, Wt);
    ln_kernel<<<dim3(Ssz / 32, Bbat, 2), 256>>>(x_l, x_r, g1, b1, g2, b2,
                                                xln, xln + BSC);

    for (int s = 0; s < 2; s++) {
        gemm_h<0><<<dim3(144, 1), 256, SMEM_GM>>>(xln + s * BSC, 256, 0,
                                                  Wt + 0 * 65536, 256, 0,
                                                  q + s * BSC, 0, 256, nullptr);
        gemm_h<0><<<dim3(144, 1), 256, SMEM_GM>>>(xln + s * BSC, 256, 0,
                                                  Wt + 1 * 65536, 256, 0,
                                                  k + s * BSC, 0, 256, nullptr);
        gemm_h<1><<<dim3(144, 1), 256, SMEM_GM>>>(xln + s * BSC, 256, 0,
                                                  Wt + 2 * 65536, 256, 0,
                                                  vt + s * BSC, 0, 256, nullptr);
    }

    for (int s = 0; s < 2; s++) {
        sc_h<<<dim3(9, 18), 256, SMEM_SC>>>(q + s * BSC, k + (1 - s) * BSC, E);
        normalize_h<<<(int)(SSl / 2048), 256>>>(E);
        gemm_h<0><<<dim3(18, 8), 256, SMEM_GM>>>(E, Ssz, SSl,
                                                 vt + s * BSC, Ssz, (long)Csz * Ssz,
                                                 O, (long)Ssz * Csz, Ssz, nullptr);
        gemm_h<2><<<dim3(144, 1), 256, SMEM_GM>>>(O, 256, 0,
                                                  Wt + 3 * 65536, 256, 0,
                                                  out + s * BSC, 0, 256,
                                                  s ? x_r : x_l);
    }
}

// round 13
// speedup vs baseline: 2.3763x; 1.2379x over previous
#include <cuda_runtime.h>
#include <cuda_fp16.h>
#include <cstdint>

#define Ssz   2304
#define Csz   256
#define Bbat  8
#define BSC   (Bbat*Ssz*Csz)
#define SSl   ((long)Ssz*Ssz)
#define ESIDE ((long)Bbat*Ssz*Ssz)

// ---- scratch (fp16 intermediates) ------------------------------------------
__device__ __half g_xln[2][BSC];
__device__ __half g_q[2][BSC];
__device__ __half g_k[2][BSC];
__device__ __half g_vt[2][BSC];            // V^T: [b][c][t]
__device__ __half g_E[2][(size_t)Bbat*Ssz*Ssz];
__device__ __half g_O[2][BSC];
__device__ __half g_Wt[4][Csz*Csz];        // W^T [n][k] fp16

// ---- helpers ---------------------------------------------------------------
__device__ __forceinline__ void mma_f16(float acc[4], const unsigned a[4], const unsigned b[2]) {
    asm volatile(
        "mma.sync.aligned.m16n8k16.row.col.f32.f16.f16.f32 "
        "{%0,%1,%2,%3}, {%4,%5,%6,%7}, {%8,%9}, {%0,%1,%2,%3};\n"
        : "+f"(acc[0]), "+f"(acc[1]), "+f"(acc[2]), "+f"(acc[3])
        : "r"(a[0]), "r"(a[1]), "r"(a[2]), "r"(a[3]), "r"(b[0]), "r"(b[1]));
}
__device__ __forceinline__ void ldsm4(unsigned &r0, unsigned &r1, unsigned &r2, unsigned &r3,
                                      unsigned addr) {
    asm volatile("ldmatrix.sync.aligned.m8n8.x4.shared.b16 {%0,%1,%2,%3}, [%4];"
        : "=r"(r0), "=r"(r1), "=r"(r2), "=r"(r3) : "r"(addr));
}
__device__ __forceinline__ void cpa16(unsigned dst, const void* src) {
    asm volatile("cp.async.cg.shared.global [%0], [%1], 16;" :: "r"(dst), "l"(src));
}
#define CP_COMMIT() asm volatile("cp.async.commit_group;" ::: "memory")
#define CP_WAIT2()  asm volatile("cp.async.wait_group 2;" ::: "memory")

// XOR-swizzled smem: rows of 32 halfs (64B), 16B segs swizzled by (r + r>>2)&3
__device__ __forceinline__ int swx(int r) { return (r + (r >> 2)) & 3; }
__device__ __forceinline__ unsigned smaddr(unsigned base, int r, int seg) {
    return base + r * 64 + ((seg ^ swx(r)) << 4);
}

// stage: A 128 rows x 64B = 8192 | B 256 rows x 64B = 16384 -> 24576 B, 4 stages
#define STG_B   24576
#define SMEM_GM (4*STG_B)   // 98304 (also covers MODE1 transpose buf 69632)
#define SMEM_SC (4*STG_B)

// ---- weight convert: W[k][n] fp32 -> Wt[n][k] fp16 -------------------------
__global__ void wconv_h(const float* __restrict__ wq, const float* __restrict__ wk,
                        const float* __restrict__ wv, const float* __restrict__ wo,
                        __half* __restrict__ wt) {
    int mat = blockIdx.y;
    const float* w = mat == 0 ? wq : mat == 1 ? wk : mat == 2 ? wv : wo;
    int k = blockIdx.x, n = threadIdx.x;
    wt[mat * 65536 + n * 256 + k] = __float2half_rn(w[k * 256 + n]);
}

// ---- LayerNorm over C + transpose [B,C,S]->[B,S,C], fp16 out ---------------
__global__ __launch_bounds__(256, 2) void ln_kernel(
    const float* __restrict__ xl, const float* __restrict__ xr,
    const float* __restrict__ g1, const float* __restrict__ b1,
    const float* __restrict__ g2, const float* __restrict__ b2,
    __half* __restrict__ xlnL, __half* __restrict__ xlnR)
{
    const int side = blockIdx.z;
    const float* x  = side ? xr : xl;
    const float* g  = side ? g2 : g1;
    const float* bb = side ? b2 : b1;
    __half* xo = side ? xlnR : xlnL;

    const int b  = blockIdx.y;
    const int s0 = blockIdx.x * 32;
    const int tid = threadIdx.x;
    const int tx = tid & 31, ty = tid >> 5;

    __shared__ float xs[256][33];
    __shared__ float ps[8][32], ps2[8][32];
    __shared__ float mu[32], rs[32];

    const float* xb = x + (size_t)b * Csz * Ssz;
    #pragma unroll
    for (int cc = 0; cc < 32; cc++) {
        int c = cc * 8 + ty;
        xs[c][tx] = xb[(size_t)c * Ssz + s0 + tx];
    }
    __syncthreads();

    float sum = 0.f, sq = 0.f;
    #pragma unroll
    for (int i = 0; i < 32; i++) {
        float v = xs[ty * 32 + i][tx];
        sum += v; sq += v * v;
    }
    ps[ty][tx] = sum; ps2[ty][tx] = sq;
    __syncthreads();

    if (ty == 0) {
        float s1 = 0.f, s2 = 0.f;
        #pragma unroll
        for (int j = 0; j < 8; j++) { s1 += ps[j][tx]; s2 += ps2[j][tx]; }
        float m = s1 * (1.f / 256.f);
        float v = s2 * (1.f / 256.f) - m * m;
        mu[tx] = m;
        rs[tx] = rsqrtf(v + 1e-5f);
    }
    __syncthreads();

    const float gc = g[tid], bc = bb[tid];
    __half* xob = xo + ((size_t)b * Ssz + s0) * Csz;
    #pragma unroll
    for (int si = 0; si < 32; si++)
        xob[si * Csz + tid] = __float2half_rn((xs[tid][si] - mu[si]) * rs[si] * gc + bc);
}

// ---- fp16 GEMM: C[M,256] = A[M,K] @ Bt[N=256,K]^T (NT, both k-contig) ------
// CTA 128x256, 256 thr, 8 warps (2m x 4n), warp tile 64x64, K-chunk 32,
// 4-stage cp.async pipeline, fragment loads via ldmatrix.x4.
// z = blockIdx.y (batch), zs = blockIdx.z (side): operand offsets sX + sX2.
// MODE 0: C fp16 [m][n].  MODE 1: Vt via smem transpose.  MODE 2: resid fp32.
template<int MODE>
__global__ __launch_bounds__(256, 1) void gemm_h(
    const __half* __restrict__ A, int lda, long sA, long sA2,
    const __half* __restrict__ Bt, int ldb, long sB, long sB2,
    void* __restrict__ Cv, long sC, long sC2, int K,
    const float* __restrict__ resid)
{
    extern __shared__ char smc[];
    const int tid = threadIdx.x, lane = tid & 31, wid = tid >> 5;
    const int grp = lane >> 2, tg = lane & 3;
    const int wm = (wid & 1) * 64, wn = (wid >> 1) * 64;
    const int m0 = blockIdx.x * 128;
    const int z = blockIdx.y, zs = blockIdx.z;
    A  += (long)z * sA + (long)zs * sA2;
    Bt += (long)z * sB + (long)zs * sB2;

    const unsigned sbu = (unsigned)__cvta_generic_to_shared(smc);
    const int la  = lane & 7;
    const int lb8 = ((lane >> 3) & 1) * 8;
    const int lc16 = lane >> 4;
    const int arow0 = wm + la + lb8;
    const int brow0 = wn + la + (lane >> 4) * 8;
    const int bseg0 = (lane >> 3) & 1;

    auto ldgsts = [&](int kc, int stg) {
        unsigned Asu = sbu + stg * STG_B;
        unsigned Bsu = Asu + 8192;
        #pragma unroll
        for (int p = 0; p < 2; p++) {
            int idx = p * 256 + tid, row = idx >> 2, sg = idx & 3;
            cpa16(smaddr(Asu, row, sg), &A[(long)(m0 + row) * lda + kc * 32 + sg * 8]);
        }
        #pragma unroll
        for (int p = 0; p < 4; p++) {
            int idx = p * 256 + tid, row = idx >> 2, sg = idx & 3;
            cpa16(smaddr(Bsu, row, sg), &Bt[(long)row * ldb + kc * 32 + sg * 8]);
        }
    };

    float acc[4][8][4];
    #pragma unroll
    for (int i = 0; i < 4; i++)
        #pragma unroll
        for (int j = 0; j < 8; j++)
            #pragma unroll
            for (int r = 0; r < 4; r++) acc[i][j][r] = 0.f;

    const int nch = K >> 5;
    #pragma unroll
    for (int p = 0; p < 3; p++) { ldgsts(p, p); CP_COMMIT(); }

    for (int ic = 0; ic < nch; ic++) {
        CP_WAIT2();
        __syncthreads();
        const unsigned Asu = sbu + (ic & 3) * STG_B;
        const unsigned Bsu = Asu + 8192;
        #pragma unroll
        for (int ks = 0; ks < 2; ks++) {
            const int s0seg = ks * 2;
            unsigned af[4][4], bf[8][2];
            #pragma unroll
            for (int mi = 0; mi < 4; mi++)
                ldsm4(af[mi][0], af[mi][1], af[mi][2], af[mi][3],
                      smaddr(Asu, arow0 + mi * 16, s0seg + lc16));
            #pragma unroll
            for (int np = 0; np < 4; np++)
                ldsm4(bf[2 * np][0], bf[2 * np][1], bf[2 * np + 1][0], bf[2 * np + 1][1],
                      smaddr(Bsu, brow0 + np * 16, s0seg + bseg0));
            #pragma unroll
            for (int mi = 0; mi < 4; mi++)
                #pragma unroll
                for (int ni = 0; ni < 8; ni++)
                    mma_f16(acc[mi][ni], af[mi], bf[ni]);
        }
        if (ic + 3 < nch) ldgsts(ic + 3, (ic + 3) & 3);
        CP_COMMIT();
    }

    if (MODE == 0) {
        __half* C = (__half*)Cv + (long)z * sC + (long)zs * sC2;
        #pragma unroll
        for (int mi = 0; mi < 4; mi++) {
            #pragma unroll
            for (int ni = 0; ni < 8; ni++) {
                int r0 = m0 + wm + mi * 16 + grp;
                int c0 = wn + ni * 8 + tg * 2;
                *(__half2*)&C[(long)r0 * 256 + c0] =
                    __floats2half2_rn(acc[mi][ni][0], acc[mi][ni][1]);
                *(__half2*)&C[(long)(r0 + 8) * 256 + c0] =
                    __floats2half2_rn(acc[mi][ni][2], acc[mi][ni][3]);
            }
        }
    } else if (MODE == 1) {
        __syncthreads();
        __half* tb = (__half*)smc;              // [256][136]
        #pragma unroll
        for (int mi = 0; mi < 4; mi++) {
            #pragma unroll
            for (int ni = 0; ni < 8; ni++) {
                int r  = wm + mi * 16 + grp;
                int c0 = wn + ni * 8 + tg * 2;
                tb[c0 * 136 + r]           = __float2half_rn(acc[mi][ni][0]);
                tb[(c0 + 1) * 136 + r]     = __float2half_rn(acc[mi][ni][1]);
                tb[c0 * 136 + r + 8]       = __float2half_rn(acc[mi][ni][2]);
                tb[(c0 + 1) * 136 + r + 8] = __float2half_rn(acc[mi][ni][3]);
            }
        }
        __syncthreads();
        const int bb = m0 / Ssz, s0m = m0 - bb * Ssz;
        __half* C = (__half*)Cv;
        #pragma unroll
        for (int p = 0; p < 16; p++) {
            int idx = p * 256 + tid;
            int c = idx >> 4, ms = idx & 15;
            uint4 v = *(uint4*)&tb[c * 136 + ms * 8];
            *(uint4*)&C[((long)(bb * 256 + c)) * Ssz + s0m + ms * 8] = v;
        }
    } else {
        float* C = (float*)Cv;
        #pragma unroll
        for (int mi = 0; mi < 4; mi++) {
            #pragma unroll
            for (int ni = 0; ni < 8; ni++) {
                int r0 = m0 + wm + mi * 16 + grp;
                int c0 = wn + ni * 8 + tg * 2;
                int bb = r0 / Ssz;
                int ss = r0 - bb * Ssz;
                long a0 = ((long)(bb * 256 + c0)) * Ssz + ss;
                C[a0          ] = resid[a0          ] + acc[mi][ni][0];
                C[a0 + Ssz    ] = resid[a0 + Ssz    ] + acc[mi][ni][1];
                C[a0 + 8      ] = resid[a0 + 8      ] + acc[mi][ni][2];
                C[a0 + Ssz + 8] = resid[a0 + Ssz + 8] + acc[mi][ni][3];
            }
        }
    }
}

// ---- scores: E[side,b,s,t] = exp(Q·K^T / 16) fp16, 8 batches per CTA -------
// grid (9 t-tiles, 18 s-tiles, 2 sides); CTA 128s x 256t, 256 thr, warp 64x64.
__global__ __launch_bounds__(256, 1) void sc_h(
    const __half* __restrict__ qb, const __half* __restrict__ kb,
    __half* __restrict__ Eg)
{
    extern __shared__ char smc[];
    const int tid = threadIdx.x, lane = tid & 31, wid = tid >> 5;
    const int grp = lane >> 2, tg = lane & 3;
    const int wm = (wid & 1) * 64, wn = (wid >> 1) * 64;
    const int s0 = blockIdx.y * 128, t0 = blockIdx.x * 256;
    const int side = blockIdx.z;

    const __half* Q  = qb + (long)side * BSC;
    const __half* Ko = kb + (long)(side ^ 1) * BSC;
    __half* E = Eg + (long)side * ESIDE;

    const unsigned sbu = (unsigned)__cvta_generic_to_shared(smc);
    const int la  = lane & 7;
    const int lb8 = ((lane >> 3) & 1) * 8;
    const int lc16 = lane >> 4;
    const int arow0 = wm + la + lb8;
    const int brow0 = wn + la + (lane >> 4) * 8;
    const int bseg0 = (lane >> 3) & 1;

    auto ldgsts = [&](int it, int stg) {
        int b = it >> 3, kc = it & 7;
        const __half* qa = Q  + ((long)b * Ssz + s0) * 256;
        const __half* ka = Ko + ((long)b * Ssz + t0) * 256;
        unsigned Asu = sbu + stg * STG_B;
        unsigned Bsu = Asu + 8192;
        #pragma unroll
        for (int p = 0; p < 2; p++) {
            int idx = p * 256 + tid, row = idx >> 2, sg = idx & 3;
            cpa16(smaddr(Asu, row, sg), &qa[(long)row * 256 + kc * 32 + sg * 8]);
        }
        #pragma unroll
        for (int p = 0; p < 4; p++) {
            int idx = p * 256 + tid, row = idx >> 2, sg = idx & 3;
            cpa16(smaddr(Bsu, row, sg), &ka[(long)row * 256 + kc * 32 + sg * 8]);
        }
    };

    float acc[4][8][4];
    #pragma unroll
    for (int p = 0; p < 3; p++) { ldgsts(p, p); CP_COMMIT(); }

    for (int it = 0; it < 64; it++) {
        CP_WAIT2();
        __syncthreads();

        if ((it & 7) == 0) {
            #pragma unroll
            for (int i = 0; i < 4; i++)
                #pragma unroll
                for (int j = 0; j < 8; j++)
                    #pragma unroll
                    for (int r = 0; r < 4; r++) acc[i][j][r] = 0.f;
        }

        const unsigned Asu = sbu + (it & 3) * STG_B;
        const unsigned Bsu = Asu + 8192;
        #pragma unroll
        for (int ks = 0; ks < 2; ks++) {
            const int s0seg = ks * 2;
            unsigned af[4][4], bf[8][2];
            #pragma unroll
            for (int mi = 0; mi < 4; mi++)
                ldsm4(af[mi][0], af[mi][1], af[mi][2], af[mi][3],
                      smaddr(Asu, arow0 + mi * 16, s0seg + lc16));
            #pragma unroll
            for (int np = 0; np < 4; np++)
                ldsm4(bf[2 * np][0], bf[2 * np][1], bf[2 * np + 1][0], bf[2 * np + 1][1],
                      smaddr(Bsu, brow0 + np * 16, s0seg + bseg0));
            #pragma unroll
            for (int mi = 0; mi < 4; mi++)
                #pragma unroll
                for (int ni = 0; ni < 8; ni++)
                    mma_f16(acc[mi][ni], af[mi], bf[ni]);
        }

        if ((it & 7) == 7) {
            const int b = it >> 3;
            __half* Eb = E + (long)b * SSl;
            #pragma unroll
            for (int mi = 0; mi < 4; mi++) {
                #pragma unroll
                for (int ni = 0; ni < 8; ni++) {
                    int r0 = s0 + wm + mi * 16 + grp;
                    int c0 = t0 + wn + ni * 8 + tg * 2;
                    *(__half2*)&Eb[(long)r0 * Ssz + c0] =
                        __floats2half2_rn(__expf(acc[mi][ni][0] * 0.0625f),
                                          __expf(acc[mi][ni][1] * 0.0625f));
                    *(__half2*)&Eb[(long)(r0 + 8) * Ssz + c0] =
                        __floats2half2_rn(__expf(acc[mi][ni][2] * 0.0625f),
                                          __expf(acc[mi][ni][3] * 0.0625f));
                }
            }
        }
        if (it + 3 < 64) ldgsts(it + 3, (it + 3) & 3);
        CP_COMMIT();
    }
}

// ---- normalize: E[b,s,t] /= sum_b E[b,s,t] (fp16, in place, per side) ------
__global__ __launch_bounds__(256, 4) void normalize_h(__half* __restrict__ Eg)
{
    __half* E = Eg + (long)blockIdx.y * ESIDE;
    long i = ((long)blockIdx.x * 256 + threadIdx.x) * 8;
    uint4 ev[Bbat];
    float s[8] = {0.f, 0.f, 0.f, 0.f, 0.f, 0.f, 0.f, 0.f};
    #pragma unroll
    for (int b = 0; b < Bbat; b++) {
        ev[b] = *(const uint4*)&E[b * SSl + i];
        const __half2* h2 = (const __half2*)&ev[b];
        #pragma unroll
        for (int j = 0; j < 4; j++) {
            float2 f = __half22float2(h2[j]);
            s[2 * j] += f.x; s[2 * j + 1] += f.y;
        }
    }
    float inv[8];
    #pragma unroll
    for (int j = 0; j < 8; j++) inv[j] = 1.f / s[j];
    #pragma unroll
    for (int b = 0; b < Bbat; b++) {
        __half2* h2 = (__half2*)&ev[b];
        #pragma unroll
        for (int j = 0; j < 4; j++) {
            float2 f = __half22float2(h2[j]);
            h2[j] = __floats2half2_rn(f.x * inv[2 * j], f.y * inv[2 * j + 1]);
        }
        *(uint4*)&E[b * SSl + i] = ev[b];
    }
}

// ---- launch ----------------------------------------------------------------
extern "C" void kernel_launch(void* const* d_in, const int* in_sizes, int n_in,
                              void* d_out, int out_size) {
    const float* x_l = (const float*)d_in[0];
    const float* x_r = (const float*)d_in[1];
    const float* Wq  = (const float*)d_in[2];
    const float* Wk  = (const float*)d_in[3];
    const float* Wv  = (const float*)d_in[4];
    const float* Wo  = (const float*)d_in[5];
    const float* g1  = (const float*)d_in[6];
    const float* b1  = (const float*)d_in[7];
    const float* g2  = (const float*)d_in[8];
    const float* b2  = (const float*)d_in[9];
    float* out = (float*)d_out;

    __half *xln, *q, *k, *vt, *E, *O, *Wt;
    cudaGetSymbolAddress((void**)&xln, g_xln);
    cudaGetSymbolAddress((void**)&q,   g_q);
    cudaGetSymbolAddress((void**)&k,   g_k);
    cudaGetSymbolAddress((void**)&vt,  g_vt);
    cudaGetSymbolAddress((void**)&E,   g_E);
    cudaGetSymbolAddress((void**)&O,   g_O);
    cudaGetSymbolAddress((void**)&Wt,  g_Wt);

    cudaFuncSetAttribute(gemm_h<0>, cudaFuncAttributeMaxDynamicSharedMemorySize, SMEM_GM);
    cudaFuncSetAttribute(gemm_h<1>, cudaFuncAttributeMaxDynamicSharedMemorySize, SMEM_GM);
    cudaFuncSetAttribute(gemm_h<2>, cudaFuncAttributeMaxDynamicSharedMemorySize, SMEM_GM);
    cudaFuncSetAttribute(sc_h,      cudaFuncAttributeMaxDynamicSharedMemorySize, SMEM_SC);

    wconv_h<<<dim3(256, 4), 256>>>(Wq, Wk, Wv, Wo, Wt);
    ln_kernel<<<dim3(Ssz / 32, Bbat, 2), 256>>>(x_l, x_r, g1, b1, g2, b2,
                                                xln, xln + BSC);

    for (int s = 0; s < 2; s++) {
        gemm_h<0><<<dim3(144, 1, 1), 256, SMEM_GM>>>(xln + s * BSC, 256, 0, 0,
                                                     Wt + 0 * 65536, 256, 0, 0,
                                                     q + s * BSC, 0, 0, 256, nullptr);
        gemm_h<0><<<dim3(144, 1, 1), 256, SMEM_GM>>>(xln + s * BSC, 256, 0, 0,
                                                     Wt + 1 * 65536, 256, 0, 0,
                                                     k + s * BSC, 0, 0, 256, nullptr);
        gemm_h<1><<<dim3(144, 1, 1), 256, SMEM_GM>>>(xln + s * BSC, 256, 0, 0,
                                                     Wt + 2 * 65536, 256, 0, 0,
                                                     vt + s * BSC, 0, 0, 256, nullptr);
    }

    // scores for both sides in one launch (324 CTAs)
    sc_h<<<dim3(9, 18, 2), 256, SMEM_SC>>>(q, k, E);
    // batch-softmax normalize, both sides
    normalize_h<<<dim3((int)(SSl / 2048), 2), 256>>>(E);
    // PV for both sides in one launch (288 CTAs)
    gemm_h<0><<<dim3(18, Bbat, 2), 256, SMEM_GM>>>(E, Ssz, SSl, ESIDE,
                                                   vt, Ssz, (long)Csz * Ssz, (long)BSC,
                                                   O, (long)Ssz * Csz, (long)BSC,
                                                   Ssz, nullptr);
    // output projection + residual + transpose back, per side (144 CTAs each)
    for (int s = 0; s < 2; s++) {
        gemm_h<2><<<dim3(144, 1, 1), 256, SMEM_GM>>>(O + s * BSC, 256, 0, 0,
                                                     Wt + 3 * 65536, 256, 0, 0,
                                                     out + s * BSC, 0, 0, 256,
                                                     s ? x_r : x_l);
    }
}

// round 15
// speedup vs baseline: 2.7585x; 1.1608x over previous
#include <cuda_runtime.h>
#include <cuda_fp16.h>
#include <cstdint>

#define Ssz   2304
#define Csz   256
#define Bbat  8
#define BSC   (Bbat*Ssz*Csz)
#define SSl   ((long)Ssz*Ssz)
#define ESIDE ((long)Bbat*Ssz*Ssz)

// ---- scratch (fp16 intermediates) ------------------------------------------
__device__ __half g_xln[2][BSC];
__device__ __half g_q[2][BSC];
__device__ __half g_k[2][BSC];
__device__ __half g_vt[2][BSC];            // V^T: [b][c][t]
__device__ __half g_E[2][(size_t)Bbat*Ssz*Ssz];
__device__ __half g_O[2][BSC];
__device__ __half g_Wt[4][Csz*Csz];        // W^T [n][k] fp16

// ---- helpers ---------------------------------------------------------------
__device__ __forceinline__ void mma_f16(float acc[4], const unsigned a[4], const unsigned b[2]) {
    asm volatile(
        "mma.sync.aligned.m16n8k16.row.col.f32.f16.f16.f32 "
        "{%0,%1,%2,%3}, {%4,%5,%6,%7}, {%8,%9}, {%0,%1,%2,%3};\n"
        : "+f"(acc[0]), "+f"(acc[1]), "+f"(acc[2]), "+f"(acc[3])
        : "r"(a[0]), "r"(a[1]), "r"(a[2]), "r"(a[3]), "r"(b[0]), "r"(b[1]));
}
__device__ __forceinline__ void ldsm4(unsigned &r0, unsigned &r1, unsigned &r2, unsigned &r3,
                                      unsigned addr) {
    asm volatile("ldmatrix.sync.aligned.m8n8.x4.shared.b16 {%0,%1,%2,%3}, [%4];"
        : "=r"(r0), "=r"(r1), "=r"(r2), "=r"(r3) : "r"(addr));
}
__device__ __forceinline__ void cpa16(unsigned dst, const void* src) {
    asm volatile("cp.async.cg.shared.global [%0], [%1], 16;" :: "r"(dst), "l"(src));
}
#define CP_COMMIT() asm volatile("cp.async.commit_group;" ::: "memory")
#define CP_WAIT2()  asm volatile("cp.async.wait_group 2;" ::: "memory")

// XOR-swizzled smem: rows of 32 halfs (64B), 16B segs swizzled by (r + r>>2)&3
__device__ __forceinline__ int swx(int r) { return (r + (r >> 2)) & 3; }
__device__ __forceinline__ unsigned smaddr(unsigned base, int r, int seg) {
    return base + r * 64 + ((seg ^ swx(r)) << 4);
}

// stage: A 128 rows x 64B = 8192 | B 128 rows x 64B = 8192 -> 16384 B, 4 stages
#define STG_B   16384
#define SMEM_GM (4*STG_B)   // 65536 per CTA, 2 CTAs/SM (also covers MODE1 buf 34816)
#define SMEM_SC (4*STG_B)

// ---- weight convert: W[k][n] fp32 -> Wt[n][k] fp16 -------------------------
__global__ void wconv_h(const float* __restrict__ wq, const float* __restrict__ wk,
                        const float* __restrict__ wv, const float* __restrict__ wo,
                        __half* __restrict__ wt) {
    int mat = blockIdx.y;
    const float* w = mat == 0 ? wq : mat == 1 ? wk : mat == 2 ? wv : wo;
    int k = blockIdx.x, n = threadIdx.x;
    wt[mat * 65536 + n * 256 + k] = __float2half_rn(w[k * 256 + n]);
}

// ---- LayerNorm over C + transpose [B,C,S]->[B,S,C], fp16 out ---------------
__global__ __launch_bounds__(256, 2) void ln_kernel(
    const float* __restrict__ xl, const float* __restrict__ xr,
    const float* __restrict__ g1, const float* __restrict__ b1,
    const float* __restrict__ g2, const float* __restrict__ b2,
    __half* __restrict__ xlnL, __half* __restrict__ xlnR)
{
    const int side = blockIdx.z;
    const float* x  = side ? xr : xl;
    const float* g  = side ? g2 : g1;
    const float* bb = side ? b2 : b1;
    __half* xo = side ? xlnR : xlnL;

    const int b  = blockIdx.y;
    const int s0 = blockIdx.x * 32;
    const int tid = threadIdx.x;
    const int tx = tid & 31, ty = tid >> 5;

    __shared__ float xs[256][33];
    __shared__ float ps[8][32], ps2[8][32];
    __shared__ float mu[32], rs[32];

    const float* xb = x + (size_t)b * Csz * Ssz;
    #pragma unroll
    for (int cc = 0; cc < 32; cc++) {
        int c = cc * 8 + ty;
        xs[c][tx] = xb[(size_t)c * Ssz + s0 + tx];
    }
    __syncthreads();

    float sum = 0.f, sq = 0.f;
    #pragma unroll
    for (int i = 0; i < 32; i++) {
        float v = xs[ty * 32 + i][tx];
        sum += v; sq += v * v;
    }
    ps[ty][tx] = sum; ps2[ty][tx] = sq;
    __syncthreads();

    if (ty == 0) {
        float s1 = 0.f, s2 = 0.f;
        #pragma unroll
        for (int j = 0; j < 8; j++) { s1 += ps[j][tx]; s2 += ps2[j][tx]; }
        float m = s1 * (1.f / 256.f);
        float v = s2 * (1.f / 256.f) - m * m;
        mu[tx] = m;
        rs[tx] = rsqrtf(v + 1e-5f);
    }
    __syncthreads();

    const float gc = g[tid], bc = bb[tid];
    __half* xob = xo + ((size_t)b * Ssz + s0) * Csz;
    #pragma unroll
    for (int si = 0; si < 32; si++)
        xob[si * Csz + tid] = __float2half_rn((xs[tid][si] - mu[si]) * rs[si] * gc + bc);
}

// ---- fp16 GEMM: C[M,256] = A[M,K] @ Bt[256,K]^T (NT, both k-contig) --------
// CTA tile 128x128 (blockIdx.x encodes m|n), 256 thr, 8 warps (2m x 4n),
// warp tile 64x32, K-chunk 32, 4-stage cp.async, ldmatrix.x4, 2 CTAs/SM.
// z = blockIdx.y (batch), zs = blockIdx.z (side).
// MODE 0: C fp16 [m][n].  MODE 1: Vt via smem transpose.  MODE 2: resid fp32.
template<int MODE>
__global__ __launch_bounds__(256, 2) void gemm_h(
    const __half* __restrict__ A, int lda, long sA, long sA2,
    const __half* __restrict__ Bt, int ldb, long sB, long sB2,
    void* __restrict__ Cv, long sC, long sC2, int K,
    const float* __restrict__ resid_l, const float* __restrict__ resid_r)
{
    extern __shared__ char smc[];
    const int tid = threadIdx.x, lane = tid & 31, wid = tid >> 5;
    const int grp = lane >> 2, tg = lane & 3;
    const int wm = (wid & 1) * 64, wn = (wid >> 1) * 32;
    const int m0 = (blockIdx.x >> 1) * 128;
    const int n0 = (blockIdx.x & 1) * 128;
    const int z = blockIdx.y, zs = blockIdx.z;
    A  += (long)z * sA + (long)zs * sA2;
    Bt += (long)z * sB + (long)zs * sB2;

    const unsigned sbu = (unsigned)__cvta_generic_to_shared(smc);
    const int la  = lane & 7;
    const int lb8 = ((lane >> 3) & 1) * 8;
    const int lc16 = lane >> 4;
    const int arow0 = wm + la + lb8;
    const int brow0 = wn + la + (lane >> 4) * 8;
    const int bseg0 = (lane >> 3) & 1;

    auto ldgsts = [&](int kc, int stg) {
        unsigned Asu = sbu + stg * STG_B;
        unsigned Bsu = Asu + 8192;
        #pragma unroll
        for (int p = 0; p < 2; p++) {
            int idx = p * 256 + tid, row = idx >> 2, sg = idx & 3;
            cpa16(smaddr(Asu, row, sg), &A[(long)(m0 + row) * lda + kc * 32 + sg * 8]);
            cpa16(smaddr(Bsu, row, sg), &Bt[(long)(n0 + row) * ldb + kc * 32 + sg * 8]);
        }
    };

    float acc[4][4][4];
    #pragma unroll
    for (int i = 0; i < 4; i++)
        #pragma unroll
        for (int j = 0; j < 4; j++)
            #pragma unroll
            for (int r = 0; r < 4; r++) acc[i][j][r] = 0.f;

    const int nch = K >> 5;
    #pragma unroll
    for (int p = 0; p < 3; p++) { ldgsts(p, p); CP_COMMIT(); }

    for (int ic = 0; ic < nch; ic++) {
        CP_WAIT2();
        __syncthreads();
        const unsigned Asu = sbu + (ic & 3) * STG_B;
        const unsigned Bsu = Asu + 8192;
        #pragma unroll
        for (int ks = 0; ks < 2; ks++) {
            const int s0seg = ks * 2;
            unsigned af[4][4], bf[4][2];
            #pragma unroll
            for (int mi = 0; mi < 4; mi++)
                ldsm4(af[mi][0], af[mi][1], af[mi][2], af[mi][3],
                      smaddr(Asu, arow0 + mi * 16, s0seg + lc16));
            #pragma unroll
            for (int np = 0; np < 2; np++)
                ldsm4(bf[2 * np][0], bf[2 * np][1], bf[2 * np + 1][0], bf[2 * np + 1][1],
                      smaddr(Bsu, brow0 + np * 16, s0seg + bseg0));
            #pragma unroll
            for (int mi = 0; mi < 4; mi++)
                #pragma unroll
                for (int ni = 0; ni < 4; ni++)
                    mma_f16(acc[mi][ni], af[mi], bf[ni]);
        }
        if (ic + 3 < nch) ldgsts(ic + 3, (ic + 3) & 3);
        CP_COMMIT();
    }

    if (MODE == 0) {
        __half* C = (__half*)Cv + (long)z * sC + (long)zs * sC2;
        #pragma unroll
        for (int mi = 0; mi < 4; mi++) {
            #pragma unroll
            for (int ni = 0; ni < 4; ni++) {
                int r0 = m0 + wm + mi * 16 + grp;
                int c0 = n0 + wn + ni * 8 + tg * 2;
                *(__half2*)&C[(long)r0 * 256 + c0] =
                    __floats2half2_rn(acc[mi][ni][0], acc[mi][ni][1]);
                *(__half2*)&C[(long)(r0 + 8) * 256 + c0] =
                    __floats2half2_rn(acc[mi][ni][2], acc[mi][ni][3]);
            }
        }
    } else if (MODE == 1) {
        __syncthreads();
        __half* tb = (__half*)smc;              // [128][136]
        #pragma unroll
        for (int mi = 0; mi < 4; mi++) {
            #pragma unroll
            for (int ni = 0; ni < 4; ni++) {
                int r  = wm + mi * 16 + grp;
                int c0 = wn + ni * 8 + tg * 2;
                tb[c0 * 136 + r]           = __float2half_rn(acc[mi][ni][0]);
                tb[(c0 + 1) * 136 + r]     = __float2half_rn(acc[mi][ni][1]);
                tb[c0 * 136 + r + 8]       = __float2half_rn(acc[mi][ni][2]);
                tb[(c0 + 1) * 136 + r + 8] = __float2half_rn(acc[mi][ni][3]);
            }
        }
        __syncthreads();
        const int bb = m0 / Ssz, s0m = m0 - bb * Ssz;
        __half* C = (__half*)Cv + (long)z * sC + (long)zs * sC2;
        #pragma unroll
        for (int p = 0; p < 8; p++) {
            int idx = p * 256 + tid;
            int c = idx >> 4, ms = idx & 15;
            uint4 v = *(uint4*)&tb[c * 136 + ms * 8];
            *(uint4*)&C[((long)(bb * 256 + n0 + c)) * Ssz + s0m + ms * 8] = v;
        }
    } else {
        const float* resid = zs ? resid_r : resid_l;
        float* C = (float*)Cv + (long)zs * sC2;
        #pragma unroll
        for (int mi = 0; mi < 4; mi++) {
            #pragma unroll
            for (int ni = 0; ni < 4; ni++) {
                int r0 = m0 + wm + mi * 16 + grp;
                int c0 = n0 + wn + ni * 8 + tg * 2;
                int bb = r0 / Ssz;
                int ss = r0 - bb * Ssz;
                long a0 = ((long)(bb * 256 + c0)) * Ssz + ss;
                C[a0          ] = resid[a0          ] + acc[mi][ni][0];
                C[a0 + Ssz    ] = resid[a0 + Ssz    ] + acc[mi][ni][1];
                C[a0 + 8      ] = resid[a0 + 8      ] + acc[mi][ni][2];
                C[a0 + Ssz + 8] = resid[a0 + Ssz + 8] + acc[mi][ni][3];
            }
        }
    }
}

// ---- scores: E[side,b,s,t] = exp(Q·K^T / 16) fp16, 8 batches per CTA -------
// grid (18 t-tiles, 18 s-tiles, 2 sides); CTA 128s x 128t, 2 CTAs/SM.
__global__ __launch_bounds__(256, 2) void sc_h(
    const __half* __restrict__ qb, const __half* __restrict__ kb,
    __half* __restrict__ Eg)
{
    extern __shared__ char smc[];
    const int tid = threadIdx.x, lane = tid & 31, wid = tid >> 5;
    const int grp = lane >> 2, tg = lane & 3;
    const int wm = (wid & 1) * 64, wn = (wid >> 1) * 32;
    const int s0 = blockIdx.y * 128, t0 = blockIdx.x * 128;
    const int side = blockIdx.z;

    const __half* Q  = qb + (long)side * BSC;
    const __half* Ko = kb + (long)(side ^ 1) * BSC;
    __half* E = Eg + (long)side * ESIDE;

    const unsigned sbu = (unsigned)__cvta_generic_to_shared(smc);
    const int la  = lane & 7;
    const int lb8 = ((lane >> 3) & 1) * 8;
    const int lc16 = lane >> 4;
    const int arow0 = wm + la + lb8;
    const int brow0 = wn + la + (lane >> 4) * 8;
    const int bseg0 = (lane >> 3) & 1;

    auto ldgsts = [&](int it, int stg) {
        int b = it >> 3, kc = it & 7;
        const __half* qa = Q  + ((long)b * Ssz + s0) * 256;
        const __half* ka = Ko + ((long)b * Ssz + t0) * 256;
        unsigned Asu = sbu + stg * STG_B;
        unsigned Bsu = Asu + 8192;
        #pragma unroll
        for (int p = 0; p < 2; p++) {
            int idx = p * 256 + tid, row = idx >> 2, sg = idx & 3;
            cpa16(smaddr(Asu, row, sg), &qa[(long)row * 256 + kc * 32 + sg * 8]);
            cpa16(smaddr(Bsu, row, sg), &ka[(long)row * 256 + kc * 32 + sg * 8]);
        }
    };

    float acc[4][4][4];
    #pragma unroll
    for (int p = 0; p < 3; p++) { ldgsts(p, p); CP_COMMIT(); }

    for (int it = 0; it < 64; it++) {
        CP_WAIT2();
        __syncthreads();

        if ((it & 7) == 0) {
            #pragma unroll
            for (int i = 0; i < 4; i++)
                #pragma unroll
                for (int j = 0; j < 4; j++)
                    #pragma unroll
                    for (int r = 0; r < 4; r++) acc[i][j][r] = 0.f;
        }

        const unsigned Asu = sbu + (it & 3) * STG_B;
        const unsigned Bsu = Asu + 8192;
        #pragma unroll
        for (int ks = 0; ks < 2; ks++) {
            const int s0seg = ks * 2;
            unsigned af[4][4], bf[4][2];
            #pragma unroll
            for (int mi = 0; mi < 4; mi++)
                ldsm4(af[mi][0], af[mi][1], af[mi][2], af[mi][3],
                      smaddr(Asu, arow0 + mi * 16, s0seg + lc16));
            #pragma unroll
            for (int np = 0; np < 2; np++)
                ldsm4(bf[2 * np][0], bf[2 * np][1], bf[2 * np + 1][0], bf[2 * np + 1][1],
                      smaddr(Bsu, brow0 + np * 16, s0seg + bseg0));
            #pragma unroll
            for (int mi = 0; mi < 4; mi++)
                #pragma unroll
                for (int ni = 0; ni < 4; ni++)
                    mma_f16(acc[mi][ni], af[mi], bf[ni]);
        }

        if ((it & 7) == 7) {
            const int b = it >> 3;
            __half* Eb = E + (long)b * SSl;
            #pragma unroll
            for (int mi = 0; mi < 4; mi++) {
                #pragma unroll
                for (int ni = 0; ni < 4; ni++) {
                    int r0 = s0 + wm + mi * 16 + grp;
                    int c0 = t0 + wn + ni * 8 + tg * 2;
                    *(__half2*)&Eb[(long)r0 * Ssz + c0] =
                        __floats2half2_rn(__expf(acc[mi][ni][0] * 0.0625f),
                                          __expf(acc[mi][ni][1] * 0.0625f));
                    *(__half2*)&Eb[(long)(r0 + 8) * Ssz + c0] =
                        __floats2half2_rn(__expf(acc[mi][ni][2] * 0.0625f),
                                          __expf(acc[mi][ni][3] * 0.0625f));
                }
            }
        }
        if (it + 3 < 64) ldgsts(it + 3, (it + 3) & 3);
        CP_COMMIT();
    }
}

// ---- normalize: E[b,s,t] /= sum_b E[b,s,t] (fp16, in place, per side) ------
__global__ __launch_bounds__(256, 4) void normalize_h(__half* __restrict__ Eg)
{
    __half* E = Eg + (long)blockIdx.y * ESIDE;
    long i = ((long)blockIdx.x * 256 + threadIdx.x) * 8;
    uint4 ev[Bbat];
    float s[8] = {0.f, 0.f, 0.f, 0.f, 0.f, 0.f, 0.f, 0.f};
    #pragma unroll
    for (int b = 0; b < Bbat; b++) {
        ev[b] = *(const uint4*)&E[b * SSl + i];
        const __half2* h2 = (const __half2*)&ev[b];
        #pragma unroll
        for (int j = 0; j < 4; j++) {
            float2 f = __half22float2(h2[j]);
            s[2 * j] += f.x; s[2 * j + 1] += f.y;
        }
    }
    float inv[8];
    #pragma unroll
    for (int j = 0; j < 8; j++) inv[j] = 1.f / s[j];
    #pragma unroll
    for (int b = 0; b < Bbat; b++) {
        __half2* h2 = (__half2*)&ev[b];
        #pragma unroll
        for (int j = 0; j < 4; j++) {
            float2 f = __half22float2(h2[j]);
            h2[j] = __floats2half2_rn(f.x * inv[2 * j], f.y * inv[2 * j + 1]);
        }
        *(uint4*)&E[b * SSl + i] = ev[b];
    }
}

// ---- launch ----------------------------------------------------------------
extern "C" void kernel_launch(void* const* d_in, const int* in_sizes, int n_in,
                              void* d_out, int out_size) {
    const float* x_l = (const float*)d_in[0];
    const float* x_r = (const float*)d_in[1];
    const float* Wq  = (const float*)d_in[2];
    const float* Wk  = (const float*)d_in[3];
    const float* Wv  = (const float*)d_in[4];
    const float* Wo  = (const float*)d_in[5];
    const float* g1  = (const float*)d_in[6];
    const float* b1  = (const float*)d_in[7];
    const float* g2  = (const float*)d_in[8];
    const float* b2  = (const float*)d_in[9];
    float* out = (float*)d_out;

    __half *xln, *q, *k, *vt, *E, *O, *Wt;
    cudaGetSymbolAddress((void**)&xln, g_xln);
    cudaGetSymbolAddress((void**)&q,   g_q);
    cudaGetSymbolAddress((void**)&k,   g_k);
    cudaGetSymbolAddress((void**)&vt,  g_vt);
    cudaGetSymbolAddress((void**)&E,   g_E);
    cudaGetSymbolAddress((void**)&O,   g_O);
    cudaGetSymbolAddress((void**)&Wt,  g_Wt);

    cudaFuncSetAttribute(gemm_h<0>, cudaFuncAttributeMaxDynamicSharedMemorySize, SMEM_GM);
    cudaFuncSetAttribute(gemm_h<1>, cudaFuncAttributeMaxDynamicSharedMemorySize, SMEM_GM);
    cudaFuncSetAttribute(gemm_h<2>, cudaFuncAttributeMaxDynamicSharedMemorySize, SMEM_GM);
    cudaFuncSetAttribute(sc_h,      cudaFuncAttributeMaxDynamicSharedMemorySize, SMEM_SC);

    wconv_h<<<dim3(256, 4), 256>>>(Wq, Wk, Wv, Wo, Wt);
    ln_kernel<<<dim3(Ssz / 32, Bbat, 2), 256>>>(x_l, x_r, g1, b1, g2, b2,
                                                xln, xln + BSC);

    // Q, K, V projections — both sides per launch (288 CTAs x 2 sides)
    gemm_h<0><<<dim3(288, 1, 2), 256, SMEM_GM>>>(xln, 256, 0, BSC,
                                                 Wt + 0 * 65536, 256, 0, 0,
                                                 q, 0, BSC, 256, nullptr, nullptr);
    gemm_h<0><<<dim3(288, 1, 2), 256, SMEM_GM>>>(xln, 256, 0, BSC,
                                                 Wt + 1 * 65536, 256, 0, 0,
                                                 k, 0, BSC, 256, nullptr, nullptr);
    gemm_h<1><<<dim3(288, 1, 2), 256, SMEM_GM>>>(xln, 256, 0, BSC,
                                                 Wt + 2 * 65536, 256, 0, 0,
                                                 vt, 0, BSC, 256, nullptr, nullptr);

    // scores for both sides (648 CTAs)
    sc_h<<<dim3(18, 18, 2), 256, SMEM_SC>>>(q, k, E);
    // batch-softmax normalize, both sides
    normalize_h<<<dim3((int)(SSl / 2048), 2), 256>>>(E);
    // PV for both sides (576 CTAs): O[b][s][c] = P[b] @ Vt[b]^T
    gemm_h<0><<<dim3(36, Bbat, 2), 256, SMEM_GM>>>(E, Ssz, SSl, ESIDE,
                                                   vt, Ssz, (long)Csz * Ssz, (long)BSC,
                                                   O, (long)Ssz * Csz, (long)BSC,
                                                   Ssz, nullptr, nullptr);
    // output projection + residual + transpose back, both sides (576 CTAs)
    gemm_h<2><<<dim3(288, 1, 2), 256, SMEM_GM>>>(O, 256, 0, BSC,
                                                 Wt + 3 * 65536, 256, 0, 0,
                                                 out, 0, BSC, 256, x_l, x_r);
}